// round 1
// baseline (speedup 1.0000x reference)
#include <cuda_runtime.h>
#include <math.h>

// Problem constants (match reference; runtime sizes cross-checked from in_sizes)
#define MAXN 50000
#define MAXE 800000
#define MAXEPN (MAXE + MAXN)

// ---------------- scratch (device globals; no allocation allowed) ----------
__device__ float    g_h1[MAXN * 256];     // layer1 GEMM output  [N,4,64]
__device__ float    g_out1[MAXN * 256];   // layer1 aggregated + elu
__device__ float    g_h2[MAXN * 64];      // layer2 GEMM output  [N,1,64]
__device__ float    g_as1[MAXN * 4], g_ad1[MAXN * 4];
__device__ float    g_as2[MAXN],     g_ad2[MAXN];
__device__ unsigned g_mkey1[MAXN * 4];
__device__ unsigned g_mkey2[MAXN];
__device__ float    g_den1[MAXN * 4];
__device__ float    g_den2[MAXN];
__device__ float    g_e1[MAXEPN * 4];     // per-edge attention scratch (e then ex)
__device__ float    g_e2[MAXEPN];

// ---------------- helpers ---------------------------------------------------
__device__ __forceinline__ unsigned f2o(float f) {
    unsigned b = __float_as_uint(f);
    return (b & 0x80000000u) ? ~b : (b | 0x80000000u);
}
__device__ __forceinline__ float o2f(unsigned u) {
    unsigned b = (u & 0x80000000u) ? (u & 0x7FFFFFFFu) : ~u;
    return __uint_as_float(b);
}

// ---------------- init ------------------------------------------------------
__global__ void init_kernel(float* dout, int n) {
    int i = blockIdx.x * blockDim.x + threadIdx.x;
    int stride = gridDim.x * blockDim.x;
    for (int j = i; j < n * 256; j += stride) g_out1[j] = 0.f;
    for (int j = i; j < n * 64;  j += stride) dout[j]   = 0.f;
    for (int j = i; j < n * 4;   j += stride) { g_mkey1[j] = 0u; g_den1[j] = 0.f; }
    for (int j = i; j < n;       j += stride) { g_mkey2[j] = 0u; g_den2[j] = 0.f; }
}

// ---------------- GEMM: C[n,m] = A[n,k] @ B[k,m] ----------------------------
// BM=128, BN=64, BK=16, per-thread 8x4, 256 threads.
__global__ void gemm_kernel(const float* __restrict__ A, const float* __restrict__ B,
                            float* __restrict__ C, int n, int k, int m) {
    __shared__ float As[16][129];
    __shared__ float Bs[16][64];
    int tx = threadIdx.x, ty = threadIdx.y;
    int tid = ty * 16 + tx;
    int row0 = blockIdx.y * 128;
    int col0 = blockIdx.x * 64;
    float acc[8][4];
    #pragma unroll
    for (int i = 0; i < 8; i++)
        #pragma unroll
        for (int j = 0; j < 4; j++) acc[i][j] = 0.f;

    for (int kt = 0; kt < k; kt += 16) {
        #pragma unroll
        for (int i = 0; i < 8; i++) {
            int e = tid + 256 * i;
            int r = e >> 4, c = e & 15;
            int gr = row0 + r;
            As[c][r] = (gr < n) ? A[(long long)gr * k + kt + c] : 0.f;
        }
        #pragma unroll
        for (int i = 0; i < 4; i++) {
            int e = tid + 256 * i;
            int r = e >> 6, c = e & 63;
            Bs[r][c] = B[(kt + r) * m + col0 + c];
        }
        __syncthreads();
        #pragma unroll
        for (int kk = 0; kk < 16; kk++) {
            float a[8], b[4];
            #pragma unroll
            for (int i = 0; i < 8; i++) a[i] = As[kk][ty * 8 + i];
            #pragma unroll
            for (int j = 0; j < 4; j++) b[j] = Bs[kk][tx * 4 + j];
            #pragma unroll
            for (int i = 0; i < 8; i++)
                #pragma unroll
                for (int j = 0; j < 4; j++) acc[i][j] += a[i] * b[j];
        }
        __syncthreads();
    }
    #pragma unroll
    for (int i = 0; i < 8; i++) {
        int gr = row0 + ty * 8 + i;
        if (gr < n) {
            #pragma unroll
            for (int j = 0; j < 4; j++)
                C[(long long)gr * m + col0 + tx * 4 + j] = acc[i][j];
        }
    }
}

// ---------------- per-node attention coefficients (one warp / node) --------
__global__ void alpha_kernel(const float* __restrict__ hm, const float* __restrict__ atts,
                             const float* __restrict__ attd, float* __restrict__ as_,
                             float* __restrict__ ad_, int n, int heads, int c) {
    int gt = blockIdx.x * blockDim.x + threadIdx.x;
    int node = gt >> 5, lane = gt & 31;
    if (node >= n) return;
    for (int h = 0; h < heads; h++) {
        float ss = 0.f, sd = 0.f;
        for (int j = lane; j < c; j += 32) {
            float v = hm[(node * heads + h) * c + j];
            ss += v * atts[h * c + j];
            sd += v * attd[h * c + j];
        }
        #pragma unroll
        for (int o = 16; o; o >>= 1) {
            ss += __shfl_down_sync(0xffffffffu, ss, o);
            sd += __shfl_down_sync(0xffffffffu, sd, o);
        }
        if (lane == 0) { as_[node * heads + h] = ss; ad_[node * heads + h] = sd; }
    }
}

// ---------------- edge pass 1: e = lrelu(as[s]+ad[d]); segment max ----------
__global__ void edge_max_kernel(const int* __restrict__ ei, int E, int n,
                                const float* __restrict__ as_, const float* __restrict__ ad_,
                                float* __restrict__ eout, unsigned* __restrict__ mkey,
                                int heads) {
    int idx = blockIdx.x * blockDim.x + threadIdx.x;
    int nume = E + n;
    if (idx >= nume) return;
    int s, d;
    if (idx < E) { s = ei[idx]; d = ei[E + idx]; } else { s = d = idx - E; }
    for (int h = 0; h < heads; h++) {
        float v = as_[s * heads + h] + ad_[d * heads + h];
        v = (v > 0.f) ? v : 0.2f * v;
        eout[idx * heads + h] = v;
        atomicMax(&mkey[d * heads + h], f2o(v));
    }
}

// ---------------- edge pass 2: ex = exp(e - m); segment sum ----------------
__global__ void edge_exp_kernel(const int* __restrict__ ei, int E, int n,
                                float* __restrict__ eout, const unsigned* __restrict__ mkey,
                                float* __restrict__ den, int heads) {
    int idx = blockIdx.x * blockDim.x + threadIdx.x;
    int nume = E + n;
    if (idx >= nume) return;
    int d;
    if (idx < E) { d = ei[E + idx]; } else { d = idx - E; }
    for (int h = 0; h < heads; h++) {
        float m = o2f(mkey[d * heads + h]);
        float ex = expf(eout[idx * heads + h] - m);
        eout[idx * heads + h] = ex;
        atomicAdd(&den[d * heads + h], ex);
    }
}

// ---------------- edge pass 3: aggregate msg = h[src]*alpha into out[dst] ---
// blockDim.x = 256; edges_per_block = 256/totch; c-per-head is 64 (ch>>6).
__global__ void agg_kernel(const int* __restrict__ ei, int E, int n,
                           const float* __restrict__ ex, const float* __restrict__ den,
                           const float* __restrict__ hm, float* __restrict__ out,
                           int heads, int totch) {
    int tid = threadIdx.x;
    int per = blockDim.x / totch;
    int edge = blockIdx.x * per + tid / totch;
    int ch = tid % totch;
    int nume = E + n;
    if (edge >= nume) return;
    int s, d;
    if (edge < E) { s = ei[edge]; d = ei[E + edge]; } else { s = d = edge - E; }
    int h = ch >> 6;
    float a = ex[edge * heads + h] / (den[d * heads + h] + 1e-16f);
    atomicAdd(&out[d * totch + ch], hm[s * totch + ch] * a);
}

// ---------------- elementwise: bias + ELU -----------------------------------
__global__ void bias_elu_kernel(float* __restrict__ out, const float* __restrict__ b,
                                int total, int totch) {
    int i = blockIdx.x * blockDim.x + threadIdx.x;
    if (i >= total) return;
    float v = out[i] + b[i % totch];
    out[i] = (v > 0.f) ? v : (expf(v) - 1.f);
}

__global__ void bias_add_kernel(float* __restrict__ out, const float* __restrict__ b,
                                int total, int totch) {
    int i = blockIdx.x * blockDim.x + threadIdx.x;
    if (i >= total) return;
    out[i] += b[i % totch];
}

// ---------------- launch ----------------------------------------------------
extern "C" void kernel_launch(void* const* d_in, const int* in_sizes, int n_in,
                              void* d_out, int out_size) {
    const float* x    = (const float*)d_in[0];
    const int*   ei   = (const int*)d_in[1];
    const float* W1   = (const float*)d_in[2];
    const float* a1s  = (const float*)d_in[3];
    const float* a1d  = (const float*)d_in[4];
    const float* b1   = (const float*)d_in[5];
    const float* W2   = (const float*)d_in[6];
    const float* a2s  = (const float*)d_in[7];
    const float* a2d  = (const float*)d_in[8];
    const float* b2   = (const float*)d_in[9];
    float* out = (float*)d_out;

    int N = in_sizes[0] / 128;
    int E = in_sizes[1] / 2;
    int EPN = E + N;

    float *h1, *out1, *h2, *as1, *ad1, *as2, *ad2, *den1, *den2, *e1, *e2;
    unsigned *mk1, *mk2;
    cudaGetSymbolAddress((void**)&h1,  g_h1);
    cudaGetSymbolAddress((void**)&out1,g_out1);
    cudaGetSymbolAddress((void**)&h2,  g_h2);
    cudaGetSymbolAddress((void**)&as1, g_as1);
    cudaGetSymbolAddress((void**)&ad1, g_ad1);
    cudaGetSymbolAddress((void**)&as2, g_as2);
    cudaGetSymbolAddress((void**)&ad2, g_ad2);
    cudaGetSymbolAddress((void**)&den1,g_den1);
    cudaGetSymbolAddress((void**)&den2,g_den2);
    cudaGetSymbolAddress((void**)&e1,  g_e1);
    cudaGetSymbolAddress((void**)&e2,  g_e2);
    cudaGetSymbolAddress((void**)&mk1, g_mkey1);
    cudaGetSymbolAddress((void**)&mk2, g_mkey2);

    dim3 tpb16(16, 16);

    // 0) zero accumulators / segment stats / output
    init_kernel<<<1024, 256>>>(out, N);

    // ---- layer 1 ----
    gemm_kernel<<<dim3(256 / 64, (N + 127) / 128), tpb16>>>(x, W1, h1, N, 128, 256);
    alpha_kernel<<<(N * 32 + 255) / 256, 256>>>(h1, a1s, a1d, as1, ad1, N, 4, 64);
    edge_max_kernel<<<(EPN + 255) / 256, 256>>>(ei, E, N, as1, ad1, e1, mk1, 4);
    edge_exp_kernel<<<(EPN + 255) / 256, 256>>>(ei, E, N, e1, mk1, den1, 4);
    agg_kernel<<<EPN, 256>>>(ei, E, N, e1, den1, h1, out1, 4, 256);
    bias_elu_kernel<<<(N * 256 + 255) / 256, 256>>>(out1, b1, N * 256, 256);

    // ---- layer 2 ----
    gemm_kernel<<<dim3(1, (N + 127) / 128), tpb16>>>(out1, W2, h2, N, 256, 64);
    alpha_kernel<<<(N * 32 + 255) / 256, 256>>>(h2, a2s, a2d, as2, ad2, N, 1, 64);
    edge_max_kernel<<<(EPN + 255) / 256, 256>>>(ei, E, N, as2, ad2, e2, mk2, 1);
    edge_exp_kernel<<<(EPN + 255) / 256, 256>>>(ei, E, N, e2, mk2, den2, 1);
    agg_kernel<<<(EPN + 3) / 4, 256>>>(ei, E, N, e2, den2, h2, out, 1, 64);
    bias_add_kernel<<<(N * 64 + 255) / 256, 256>>>(out, b2, N * 64, 64);
}

// round 2
// speedup vs baseline: 3.3539x; 3.3539x over previous
#include <cuda_runtime.h>
#include <math.h>

#define MAXN 50000
#define MAXE 800000
#define MAXEPN (MAXE + MAXN)

// ---------------- scratch (device globals) ----------------------------------
__device__ __align__(16) float g_h1[MAXN * 256];   // layer1 GEMM output [N,4,64]
__device__ __align__(16) float g_out1[MAXN * 256]; // layer1 aggregated+elu
__device__ __align__(16) float g_h2[MAXN * 64];    // layer2 GEMM output
__device__ __align__(16) float g_as1[MAXN * 4], g_ad1[MAXN * 4];
__device__ float g_as2[MAXN], g_ad2[MAXN];
__device__ __align__(16) float g_inv1[MAXN * 4];
__device__ float g_inv2[MAXN];
__device__ __align__(16) float g_exA1[MAXEPN * 4]; // softmax numerators layer1
__device__ float g_exA2[MAXEPN];
__device__ int g_deg[MAXN];
__device__ int g_rowptr[MAXN + 1];
__device__ int g_cursor[MAXN];
__device__ int g_csrc[MAXEPN];                     // CSR: src node per (dst-sorted) edge

// ---------------- init: zero degree counters only ---------------------------
__global__ void init_kernel(int n) {
    int i = blockIdx.x * blockDim.x + threadIdx.x;
    if (i < n) g_deg[i] = 0;
}

// ---------------- CSR build --------------------------------------------------
__global__ void hist_kernel(const int* __restrict__ ei, int E, int n) {
    int idx = blockIdx.x * blockDim.x + threadIdx.x;
    if (idx >= E + n) return;
    int d = (idx < E) ? ei[E + idx] : (idx - E);
    atomicAdd(&g_deg[d], 1);
}

__global__ void scan_kernel(int n) {
    __shared__ int wsum[32];
    __shared__ int carry_s;
    int lane = threadIdx.x & 31, wid = threadIdx.x >> 5;
    if (threadIdx.x == 0) carry_s = 0;
    __syncthreads();
    for (int base = 0; base < n; base += 1024) {
        int i = base + (int)threadIdx.x;
        int v = (i < n) ? g_deg[i] : 0;
        int x = v;
        #pragma unroll
        for (int o = 1; o < 32; o <<= 1) {
            int y = __shfl_up_sync(0xffffffffu, x, o);
            if (lane >= o) x += y;
        }
        if (lane == 31) wsum[wid] = x;
        __syncthreads();
        if (wid == 0) {
            int w = wsum[lane];
            int xs = w;
            #pragma unroll
            for (int o = 1; o < 32; o <<= 1) {
                int y = __shfl_up_sync(0xffffffffu, xs, o);
                if (lane >= o) xs += y;
            }
            wsum[lane] = xs - w;   // exclusive warp offsets
        }
        __syncthreads();
        int excl = carry_s + wsum[wid] + x - v;
        if (i < n) { g_rowptr[i] = excl; g_cursor[i] = excl; }
        __syncthreads();
        if (threadIdx.x == 1023) carry_s = excl + v;
        __syncthreads();
    }
    if (threadIdx.x == 0) g_rowptr[n] = carry_s;
}

__global__ void scatter_kernel(const int* __restrict__ ei, int E, int n) {
    int idx = blockIdx.x * blockDim.x + threadIdx.x;
    if (idx >= E + n) return;
    int s, d;
    if (idx < E) { s = ei[idx]; d = ei[E + idx]; } else { s = d = idx - E; }
    int pos = atomicAdd(&g_cursor[d], 1);
    g_csrc[pos] = s;
}

// ---------------- GEMM: C[n,m] = A[n,k] @ B[k,m] ----------------------------
__global__ void gemm_kernel(const float* __restrict__ A, const float* __restrict__ B,
                            float* __restrict__ C, int n, int k, int m) {
    __shared__ float As[16][129];
    __shared__ float Bs[16][64];
    int tx = threadIdx.x, ty = threadIdx.y;
    int tid = ty * 16 + tx;
    int row0 = blockIdx.y * 128;
    int col0 = blockIdx.x * 64;
    float acc[8][4];
    #pragma unroll
    for (int i = 0; i < 8; i++)
        #pragma unroll
        for (int j = 0; j < 4; j++) acc[i][j] = 0.f;

    for (int kt = 0; kt < k; kt += 16) {
        #pragma unroll
        for (int i = 0; i < 8; i++) {
            int e = tid + 256 * i;
            int r = e >> 4, c = e & 15;
            int gr = row0 + r;
            As[c][r] = (gr < n) ? A[(long long)gr * k + kt + c] : 0.f;
        }
        #pragma unroll
        for (int i = 0; i < 4; i++) {
            int e = tid + 256 * i;
            int r = e >> 6, c = e & 63;
            Bs[r][c] = B[(kt + r) * m + col0 + c];
        }
        __syncthreads();
        #pragma unroll
        for (int kk = 0; kk < 16; kk++) {
            float a[8], b[4];
            #pragma unroll
            for (int i = 0; i < 8; i++) a[i] = As[kk][ty * 8 + i];
            #pragma unroll
            for (int j = 0; j < 4; j++) b[j] = Bs[kk][tx * 4 + j];
            #pragma unroll
            for (int i = 0; i < 8; i++)
                #pragma unroll
                for (int j = 0; j < 4; j++) acc[i][j] += a[i] * b[j];
        }
        __syncthreads();
    }
    #pragma unroll
    for (int i = 0; i < 8; i++) {
        int gr = row0 + ty * 8 + i;
        if (gr < n) {
            #pragma unroll
            for (int j = 0; j < 4; j++)
                C[(long long)gr * m + col0 + tx * 4 + j] = acc[i][j];
        }
    }
}

// ---------------- per-node attention coefficients (one warp / node) ---------
__global__ void alpha_kernel(const float* __restrict__ hm, const float* __restrict__ atts,
                             const float* __restrict__ attd, float* __restrict__ as_,
                             float* __restrict__ ad_, int n, int heads, int c) {
    int gt = blockIdx.x * blockDim.x + threadIdx.x;
    int node = gt >> 5, lane = gt & 31;
    if (node >= n) return;
    for (int h = 0; h < heads; h++) {
        float ss = 0.f, sd = 0.f;
        for (int j = lane; j < c; j += 32) {
            float v = hm[(node * heads + h) * c + j];
            ss += v * atts[h * c + j];
            sd += v * attd[h * c + j];
        }
        #pragma unroll
        for (int o = 16; o; o >>= 1) {
            ss += __shfl_down_sync(0xffffffffu, ss, o);
            sd += __shfl_down_sync(0xffffffffu, sd, o);
        }
        if (lane == 0) { as_[node * heads + h] = ss; ad_[node * heads + h] = sd; }
    }
}

// ---------------- softmax over incoming edges (warp per node) ---------------
template <int H>
__global__ void softmax_kernel(const float* __restrict__ as_, const float* __restrict__ ad_,
                               float* __restrict__ exA, float* __restrict__ invden, int n) {
    int gt = blockIdx.x * blockDim.x + threadIdx.x;
    int node = gt >> 5, lane = gt & 31;
    if (node >= n) return;
    int r0 = g_rowptr[node], r1 = g_rowptr[node + 1];

    float adv[H];
    #pragma unroll
    for (int h = 0; h < H; h++) adv[h] = ad_[node * H + h];

    float mx[H];
    #pragma unroll
    for (int h = 0; h < H; h++) mx[h] = -1e30f;

    for (int j = r0 + lane; j < r1; j += 32) {
        int s = g_csrc[j];
        float ev[H];
        if (H == 4) {
            float4 a4 = reinterpret_cast<const float4*>(as_)[s];
            ev[0] = a4.x; ev[1] = a4.y; ev[2] = a4.z; ev[3] = a4.w;
        } else {
            ev[0] = as_[s];
        }
        #pragma unroll
        for (int h = 0; h < H; h++) {
            float v = ev[h] + adv[h];
            v = (v > 0.f) ? v : 0.2f * v;
            mx[h] = fmaxf(mx[h], v);
        }
    }
    #pragma unroll
    for (int h = 0; h < H; h++)
        #pragma unroll
        for (int o = 16; o; o >>= 1)
            mx[h] = fmaxf(mx[h], __shfl_xor_sync(0xffffffffu, mx[h], o));

    float sum[H];
    #pragma unroll
    for (int h = 0; h < H; h++) sum[h] = 0.f;

    for (int j = r0 + lane; j < r1; j += 32) {
        int s = g_csrc[j];
        float ev[H];
        if (H == 4) {
            float4 a4 = reinterpret_cast<const float4*>(as_)[s];
            ev[0] = a4.x; ev[1] = a4.y; ev[2] = a4.z; ev[3] = a4.w;
        } else {
            ev[0] = as_[s];
        }
        float exv[H];
        #pragma unroll
        for (int h = 0; h < H; h++) {
            float v = ev[h] + adv[h];
            v = (v > 0.f) ? v : 0.2f * v;
            float ex = __expf(v - mx[h]);
            exv[h] = ex;
            sum[h] += ex;
        }
        if (H == 4) {
            float4 w = make_float4(exv[0], exv[1], exv[2], exv[3]);
            reinterpret_cast<float4*>(exA)[j] = w;
        } else {
            exA[j] = exv[0];
        }
    }
    #pragma unroll
    for (int h = 0; h < H; h++)
        #pragma unroll
        for (int o = 16; o; o >>= 1)
            sum[h] += __shfl_xor_sync(0xffffffffu, sum[h], o);

    if (lane == 0) {
        #pragma unroll
        for (int h = 0; h < H; h++)
            invden[node * H + h] = 1.f / (sum[h] + 1e-16f);
    }
}

// ---------------- aggregation: gather per node, no atomics ------------------
// CH channels, H heads; block = 256 threads = (256/CH) nodes.
template <int CH, int H, bool ELU>
__global__ void agg_kernel(const float* __restrict__ exA, const float* __restrict__ invden,
                           const float* __restrict__ hm, const float* __restrict__ bias,
                           float* __restrict__ out, int n) {
    const int NPB = 256 / CH;
    int tid = threadIdx.x;
    int node = blockIdx.x * NPB + tid / CH;
    int ch = tid % CH;
    if (node >= n) return;
    const int h = ch / (CH / H);
    int r0 = g_rowptr[node], r1 = g_rowptr[node + 1];
    float inv = invden[node * H + h];
    float acc = 0.f;
    #pragma unroll 4
    for (int j = r0; j < r1; j++) {
        int s = g_csrc[j];
        float a = exA[j * H + h];
        acc += hm[(long long)s * CH + ch] * a;
    }
    float r = acc * inv + bias[ch];
    if (ELU) r = (r > 0.f) ? r : (__expf(r) - 1.f);
    out[(long long)node * CH + ch] = r;
}

// ---------------- launch ----------------------------------------------------
extern "C" void kernel_launch(void* const* d_in, const int* in_sizes, int n_in,
                              void* d_out, int out_size) {
    const float* x   = (const float*)d_in[0];
    const int*   ei  = (const int*)d_in[1];
    const float* W1  = (const float*)d_in[2];
    const float* a1s = (const float*)d_in[3];
    const float* a1d = (const float*)d_in[4];
    const float* b1  = (const float*)d_in[5];
    const float* W2  = (const float*)d_in[6];
    const float* a2s = (const float*)d_in[7];
    const float* a2d = (const float*)d_in[8];
    const float* b2  = (const float*)d_in[9];
    float* out = (float*)d_out;

    int N = in_sizes[0] / 128;
    int E = in_sizes[1] / 2;
    int EPN = E + N;

    float *h1, *out1, *h2, *as1, *ad1, *as2, *ad2, *inv1, *inv2, *exA1, *exA2;
    cudaGetSymbolAddress((void**)&h1,   g_h1);
    cudaGetSymbolAddress((void**)&out1, g_out1);
    cudaGetSymbolAddress((void**)&h2,   g_h2);
    cudaGetSymbolAddress((void**)&as1,  g_as1);
    cudaGetSymbolAddress((void**)&ad1,  g_ad1);
    cudaGetSymbolAddress((void**)&as2,  g_as2);
    cudaGetSymbolAddress((void**)&ad2,  g_ad2);
    cudaGetSymbolAddress((void**)&inv1, g_inv1);
    cudaGetSymbolAddress((void**)&inv2, g_inv2);
    cudaGetSymbolAddress((void**)&exA1, g_exA1);
    cudaGetSymbolAddress((void**)&exA2, g_exA2);

    dim3 tpb16(16, 16);

    // CSR build (shared by both layers)
    init_kernel<<<(N + 255) / 256, 256>>>(N);
    hist_kernel<<<(EPN + 255) / 256, 256>>>(ei, E, N);
    scan_kernel<<<1, 1024>>>(N);
    scatter_kernel<<<(EPN + 255) / 256, 256>>>(ei, E, N);

    // ---- layer 1 ----
    gemm_kernel<<<dim3(4, (N + 127) / 128), tpb16>>>(x, W1, h1, N, 128, 256);
    alpha_kernel<<<(N * 32 + 255) / 256, 256>>>(h1, a1s, a1d, as1, ad1, N, 4, 64);
    softmax_kernel<4><<<(N * 32 + 255) / 256, 256>>>(as1, ad1, exA1, inv1, N);
    agg_kernel<256, 4, true><<<N, 256>>>(exA1, inv1, h1, b1, out1, N);

    // ---- layer 2 ----
    gemm_kernel<<<dim3(1, (N + 127) / 128), tpb16>>>(out1, W2, h2, N, 256, 64);
    alpha_kernel<<<(N * 32 + 255) / 256, 256>>>(h2, a2s, a2d, as2, ad2, N, 1, 64);
    softmax_kernel<1><<<(N * 32 + 255) / 256, 256>>>(as2, ad2, exA2, inv2, N);
    agg_kernel<64, 1, false><<<(N + 3) / 4, 256>>>(exA2, inv2, h2, b2, out, N);
}

// round 3
// speedup vs baseline: 3.7386x; 1.1147x over previous
#include <cuda_runtime.h>
#include <math.h>

#define MAXN 50000
#define MAXE 800000
#define MAXEPN (MAXE + MAXN)

// ---------------- scratch (device globals) ----------------------------------
__device__ __align__(16) float g_h1[MAXN * 256];   // layer1 GEMM output [N,4,64]
__device__ __align__(16) float g_out1[MAXN * 256]; // layer1 aggregated+elu
__device__ __align__(16) float g_h2[MAXN * 64];    // layer2 GEMM output
__device__ __align__(16) float g_as1[MAXN * 4], g_ad1[MAXN * 4];
__device__ float g_as2[MAXN], g_ad2[MAXN];
__device__ __align__(16) float g_inv1[MAXN * 4];
__device__ float g_inv2[MAXN];
__device__ __align__(16) float g_exA1[MAXEPN * 4]; // softmax numerators layer1
__device__ float g_exA2[MAXEPN];
__device__ int g_deg[MAXN];
__device__ int g_rowptr[MAXN + 1];
__device__ int g_cursor[MAXN];
__device__ int g_csrc[MAXEPN];                     // CSR: src per (dst-sorted) edge
__device__ int g_bsum[64];                         // scan block sums
__device__ int g_boff[64];

// ---------------- init: zero degree counters --------------------------------
__global__ void init_kernel(int n) {
    int i = blockIdx.x * blockDim.x + threadIdx.x;
    if (i < n) g_deg[i] = 0;
}

// ---------------- CSR build --------------------------------------------------
__global__ void hist_kernel(const int* __restrict__ ei, int E, int n) {
    int idx = blockIdx.x * blockDim.x + threadIdx.x;
    if (idx >= E + n) return;
    int d = (idx < E) ? ei[E + idx] : (idx - E);
    atomicAdd(&g_deg[d], 1);
}

// pass 1: per-block (1024 elems) exclusive scan + block total
__global__ void scan_local_kernel(int n) {
    __shared__ int wsum[32];
    int lane = threadIdx.x & 31, wid = threadIdx.x >> 5;
    int i = blockIdx.x * 1024 + threadIdx.x;
    int v = (i < n) ? g_deg[i] : 0;
    int x = v;
    #pragma unroll
    for (int o = 1; o < 32; o <<= 1) {
        int y = __shfl_up_sync(0xffffffffu, x, o);
        if (lane >= o) x += y;
    }
    if (lane == 31) wsum[wid] = x;
    __syncthreads();
    if (wid == 0) {
        int w = wsum[lane];
        int xs = w;
        #pragma unroll
        for (int o = 1; o < 32; o <<= 1) {
            int y = __shfl_up_sync(0xffffffffu, xs, o);
            if (lane >= o) xs += y;
        }
        wsum[lane] = xs - w;  // exclusive warp offsets
    }
    __syncthreads();
    int excl = wsum[wid] + x - v;
    if (i < n) g_rowptr[i] = excl;
    if (threadIdx.x == 1023) g_bsum[blockIdx.x] = excl + v;
}

// pass 2: exclusive scan of block sums (<=64 entries)
__global__ void scan_bsum_kernel(int nb) {
    __shared__ int s[64];
    int t = threadIdx.x;
    s[t] = (t < nb) ? g_bsum[t] : 0;
    __syncthreads();
    // simple serial-log scan in smem (tiny)
    for (int o = 1; o < 64; o <<= 1) {
        int v = (t >= o) ? s[t - o] : 0;
        __syncthreads();
        s[t] += v;
        __syncthreads();
    }
    int incl = s[t];
    g_boff[t] = incl - ((t < nb) ? g_bsum[t] : 0);
}

// pass 3: add block offsets; init cursor; set rowptr[n]
__global__ void scan_add_kernel(int n, int total) {
    int i = blockIdx.x * blockDim.x + threadIdx.x;
    if (i < n) {
        int r = g_rowptr[i] + g_boff[i >> 10];
        g_rowptr[i] = r;
        g_cursor[i] = r;
    }
    if (i == 0) g_rowptr[n] = total;
}

__global__ void scatter_kernel(const int* __restrict__ ei, int E, int n) {
    int idx = blockIdx.x * blockDim.x + threadIdx.x;
    if (idx >= E + n) return;
    int s, d;
    if (idx < E) { s = ei[idx]; d = ei[E + idx]; } else { s = d = idx - E; }
    int pos = atomicAdd(&g_cursor[d], 1);
    g_csrc[pos] = s;
}

// ---------------- GEMM: C[n,m] = A[n,k] @ B[k,m], double-buffered -----------
template <int BM, int BN, int BK, int TM, int TN>
__global__ void gemm_kernel(const float* __restrict__ A, const float* __restrict__ B,
                            float* __restrict__ C, int n, int k, int m) {
    constexpr int THREADS = (BM / TM) * (BN / TN);
    constexpr int ASLOTS = BM * BK / 4;
    constexpr int AITER = ASLOTS / THREADS;
    constexpr int BSLOTS = BK * BN / 4;
    constexpr int BITER = BSLOTS / THREADS;

    __shared__ float As[2][BK][BM + 4];
    __shared__ float Bs[2][BK][BN];

    int tid = threadIdx.x;
    int tx = tid % (BN / TN);
    int ty = tid / (BN / TN);
    int row0 = blockIdx.y * BM, col0 = blockIdx.x * BN;

    float4 aReg[AITER], bReg[BITER];

    auto loadTile = [&](int kt) {
        #pragma unroll
        for (int i = 0; i < AITER; i++) {
            int slot = tid + i * THREADS;
            int row = slot / (BK / 4);
            int kq = slot % (BK / 4);
            int gr = row0 + row;
            aReg[i] = (gr < n)
                ? *reinterpret_cast<const float4*>(&A[(size_t)gr * k + kt + kq * 4])
                : make_float4(0.f, 0.f, 0.f, 0.f);
        }
        #pragma unroll
        for (int i = 0; i < BITER; i++) {
            int slot = tid + i * THREADS;
            int kr = slot / (BN / 4);
            int mc = slot % (BN / 4);
            bReg[i] = *reinterpret_cast<const float4*>(&B[(size_t)(kt + kr) * m + col0 + mc * 4]);
        }
    };
    auto storeTile = [&](int p) {
        #pragma unroll
        for (int i = 0; i < AITER; i++) {
            int slot = tid + i * THREADS;
            int row = slot / (BK / 4);
            int kq = slot % (BK / 4);
            As[p][kq * 4 + 0][row] = aReg[i].x;
            As[p][kq * 4 + 1][row] = aReg[i].y;
            As[p][kq * 4 + 2][row] = aReg[i].z;
            As[p][kq * 4 + 3][row] = aReg[i].w;
        }
        #pragma unroll
        for (int i = 0; i < BITER; i++) {
            int slot = tid + i * THREADS;
            int kr = slot / (BN / 4);
            int mc = slot % (BN / 4);
            *reinterpret_cast<float4*>(&Bs[p][kr][mc * 4]) = bReg[i];
        }
    };

    float acc[TM][TN] = {};
    int tiles = k / BK;
    loadTile(0);
    storeTile(0);
    __syncthreads();
    int p = 0;
    for (int t = 0; t < tiles; t++) {
        if (t + 1 < tiles) loadTile((t + 1) * BK);
        #pragma unroll
        for (int kk = 0; kk < BK; kk++) {
            float a[TM], b[TN];
            #pragma unroll
            for (int i = 0; i < TM; i++) a[i] = As[p][kk][ty * TM + i];
            #pragma unroll
            for (int j = 0; j < TN; j++) b[j] = Bs[p][kk][tx * TN + j];
            #pragma unroll
            for (int i = 0; i < TM; i++)
                #pragma unroll
                for (int j = 0; j < TN; j++) acc[i][j] += a[i] * b[j];
        }
        if (t + 1 < tiles) {
            storeTile(1 - p);
            __syncthreads();
            p ^= 1;
        }
    }
    #pragma unroll
    for (int i = 0; i < TM; i++) {
        int gr = row0 + ty * TM + i;
        if (gr < n) {
            #pragma unroll
            for (int j = 0; j < TN; j += 4) {
                float4 v = make_float4(acc[i][j], acc[i][j + 1], acc[i][j + 2], acc[i][j + 3]);
                *reinterpret_cast<float4*>(&C[(size_t)gr * m + col0 + tx * TN + j]) = v;
            }
        }
    }
}

// ---------------- per-node attention coefficients (one warp / node) ---------
__global__ void alpha_kernel(const float* __restrict__ hm, const float* __restrict__ atts,
                             const float* __restrict__ attd, float* __restrict__ as_,
                             float* __restrict__ ad_, int n, int heads, int c) {
    int gt = blockIdx.x * blockDim.x + threadIdx.x;
    int node = gt >> 5, lane = gt & 31;
    if (node >= n) return;
    for (int h = 0; h < heads; h++) {
        float ss = 0.f, sd = 0.f;
        for (int j = lane; j < c; j += 32) {
            float v = hm[(node * heads + h) * c + j];
            ss += v * atts[h * c + j];
            sd += v * attd[h * c + j];
        }
        #pragma unroll
        for (int o = 16; o; o >>= 1) {
            ss += __shfl_down_sync(0xffffffffu, ss, o);
            sd += __shfl_down_sync(0xffffffffu, sd, o);
        }
        if (lane == 0) { as_[node * heads + h] = ss; ad_[node * heads + h] = sd; }
    }
}

// ---------------- softmax over incoming edges (warp per node) ---------------
template <int H>
__global__ void softmax_kernel(const float* __restrict__ as_, const float* __restrict__ ad_,
                               float* __restrict__ exA, float* __restrict__ invden, int n) {
    int gt = blockIdx.x * blockDim.x + threadIdx.x;
    int node = gt >> 5, lane = gt & 31;
    if (node >= n) return;
    int r0 = g_rowptr[node], r1 = g_rowptr[node + 1];

    float adv[H];
    #pragma unroll
    for (int h = 0; h < H; h++) adv[h] = ad_[node * H + h];

    float mx[H];
    #pragma unroll
    for (int h = 0; h < H; h++) mx[h] = -1e30f;

    for (int j = r0 + lane; j < r1; j += 32) {
        int s = g_csrc[j];
        float ev[H];
        if (H == 4) {
            float4 a4 = reinterpret_cast<const float4*>(as_)[s];
            ev[0] = a4.x; ev[1] = a4.y; ev[2] = a4.z; ev[3] = a4.w;
        } else {
            ev[0] = as_[s];
        }
        #pragma unroll
        for (int h = 0; h < H; h++) {
            float v = ev[h] + adv[h];
            v = (v > 0.f) ? v : 0.2f * v;
            mx[h] = fmaxf(mx[h], v);
        }
    }
    #pragma unroll
    for (int h = 0; h < H; h++)
        #pragma unroll
        for (int o = 16; o; o >>= 1)
            mx[h] = fmaxf(mx[h], __shfl_xor_sync(0xffffffffu, mx[h], o));

    float sum[H];
    #pragma unroll
    for (int h = 0; h < H; h++) sum[h] = 0.f;

    for (int j = r0 + lane; j < r1; j += 32) {
        int s = g_csrc[j];
        float ev[H];
        if (H == 4) {
            float4 a4 = reinterpret_cast<const float4*>(as_)[s];
            ev[0] = a4.x; ev[1] = a4.y; ev[2] = a4.z; ev[3] = a4.w;
        } else {
            ev[0] = as_[s];
        }
        float exv[H];
        #pragma unroll
        for (int h = 0; h < H; h++) {
            float v = ev[h] + adv[h];
            v = (v > 0.f) ? v : 0.2f * v;
            float ex = __expf(v - mx[h]);
            exv[h] = ex;
            sum[h] += ex;
        }
        if (H == 4) {
            reinterpret_cast<float4*>(exA)[j] = make_float4(exv[0], exv[1], exv[2], exv[3]);
        } else {
            exA[j] = exv[0];
        }
    }
    #pragma unroll
    for (int h = 0; h < H; h++)
        #pragma unroll
        for (int o = 16; o; o >>= 1)
            sum[h] += __shfl_xor_sync(0xffffffffu, sum[h], o);

    if (lane == 0) {
        #pragma unroll
        for (int h = 0; h < H; h++)
            invden[node * H + h] = 1.f / (sum[h] + 1e-16f);
    }
}

// ---------------- aggregation layer1: 1 node/block, smem-staged -------------
__global__ void agg1_kernel(const float* __restrict__ exA, const float* __restrict__ invden,
                            const float* __restrict__ hm, const float* __restrict__ bias,
                            float* __restrict__ out, int n) {
    const int CHUNK = 64;
    __shared__ int s_src[CHUNK];
    __shared__ float s_a[CHUNK * 4];
    int tid = threadIdx.x;
    int node = blockIdx.x;
    int ch = tid;
    int h = ch >> 6;
    int r0 = g_rowptr[node], r1 = g_rowptr[node + 1];
    float inv = invden[node * 4 + h];
    float acc = 0.f;
    for (int base = r0; base < r1; base += CHUNK) {
        int cnt = min(CHUNK, r1 - base);
        if (tid < cnt) {
            s_src[tid] = g_csrc[base + tid];
            reinterpret_cast<float4*>(s_a)[tid] = reinterpret_cast<const float4*>(exA)[base + tid];
        }
        __syncthreads();
        #pragma unroll 4
        for (int j = 0; j < cnt; j++) {
            int s = s_src[j];
            acc += hm[(size_t)s * 256 + ch] * s_a[j * 4 + h];
        }
        __syncthreads();
    }
    float r = acc * inv + bias[ch];
    r = (r > 0.f) ? r : (__expf(r) - 1.f);
    out[(size_t)node * 256 + ch] = r;
}

// ---------------- aggregation layer2: 4 nodes/block, direct -----------------
__global__ void agg2_kernel(const float* __restrict__ exA, const float* __restrict__ invden,
                            const float* __restrict__ hm, const float* __restrict__ bias,
                            float* __restrict__ out, int n) {
    int tid = threadIdx.x;
    int node = blockIdx.x * 4 + tid / 64;
    int ch = tid % 64;
    if (node >= n) return;
    int r0 = g_rowptr[node], r1 = g_rowptr[node + 1];
    float inv = invden[node];
    float acc = 0.f;
    #pragma unroll 4
    for (int j = r0; j < r1; j++) {
        int s = g_csrc[j];
        acc += hm[(size_t)s * 64 + ch] * exA[j];
    }
    out[(size_t)node * 64 + ch] = acc * inv + bias[ch];
}

// ---------------- launch ----------------------------------------------------
extern "C" void kernel_launch(void* const* d_in, const int* in_sizes, int n_in,
                              void* d_out, int out_size) {
    const float* x   = (const float*)d_in[0];
    const int*   ei  = (const int*)d_in[1];
    const float* W1  = (const float*)d_in[2];
    const float* a1s = (const float*)d_in[3];
    const float* a1d = (const float*)d_in[4];
    const float* b1  = (const float*)d_in[5];
    const float* W2  = (const float*)d_in[6];
    const float* a2s = (const float*)d_in[7];
    const float* a2d = (const float*)d_in[8];
    const float* b2  = (const float*)d_in[9];
    float* out = (float*)d_out;

    int N = in_sizes[0] / 128;
    int E = in_sizes[1] / 2;
    int EPN = E + N;
    int NB = (N + 1023) / 1024;

    float *h1, *out1, *h2, *as1, *ad1, *as2, *ad2, *inv1, *inv2, *exA1, *exA2;
    cudaGetSymbolAddress((void**)&h1,   g_h1);
    cudaGetSymbolAddress((void**)&out1, g_out1);
    cudaGetSymbolAddress((void**)&h2,   g_h2);
    cudaGetSymbolAddress((void**)&as1,  g_as1);
    cudaGetSymbolAddress((void**)&ad1,  g_ad1);
    cudaGetSymbolAddress((void**)&as2,  g_as2);
    cudaGetSymbolAddress((void**)&ad2,  g_ad2);
    cudaGetSymbolAddress((void**)&inv1, g_inv1);
    cudaGetSymbolAddress((void**)&inv2, g_inv2);
    cudaGetSymbolAddress((void**)&exA1, g_exA1);
    cudaGetSymbolAddress((void**)&exA2, g_exA2);

    // CSR build (shared by both layers)
    init_kernel<<<(N + 255) / 256, 256>>>(N);
    hist_kernel<<<(EPN + 255) / 256, 256>>>(ei, E, N);
    scan_local_kernel<<<NB, 1024>>>(N);
    scan_bsum_kernel<<<1, 64>>>(NB);
    scan_add_kernel<<<(N + 255) / 256, 256>>>(N, EPN);
    scatter_kernel<<<(EPN + 255) / 256, 256>>>(ei, E, N);

    // ---- layer 1 ----
    gemm_kernel<128, 128, 16, 8, 8><<<dim3(2, (N + 127) / 128), 256>>>(x, W1, h1, N, 128, 256);
    alpha_kernel<<<(N * 32 + 255) / 256, 256>>>(h1, a1s, a1d, as1, ad1, N, 4, 64);
    softmax_kernel<4><<<(N * 32 + 255) / 256, 256>>>(as1, ad1, exA1, inv1, N);
    agg1_kernel<<<N, 256>>>(exA1, inv1, h1, b1, out1, N);

    // ---- layer 2 ----
    gemm_kernel<128, 64, 16, 8, 4><<<dim3(1, (N + 127) / 128), 256>>>(out1, W2, h2, N, 256, 64);
    alpha_kernel<<<(N * 32 + 255) / 256, 256>>>(h2, a2s, a2d, as2, ad2, N, 1, 64);
    softmax_kernel<1><<<(N * 32 + 255) / 256, 256>>>(as2, ad2, exA2, inv2, N);
    agg2_kernel<<<(N + 3) / 4, 256>>>(exA2, inv2, h2, b2, out, N);
}

// round 4
// speedup vs baseline: 3.8828x; 1.0386x over previous
#include <cuda_runtime.h>
#include <math.h>

#define MAXN 50000
#define MAXE 800000
#define MAXEPN (MAXE + MAXN)

// ---------------- scratch (device globals) ----------------------------------
__device__ __align__(16) float g_h1[MAXN * 256];   // layer1 GEMM output [N,4,64]
__device__ __align__(16) float g_out1[MAXN * 256]; // layer1 aggregated+elu
__device__ __align__(16) float g_h2[MAXN * 64];    // layer2 GEMM output
__device__ __align__(16) float g_as1[MAXN * 4], g_ad1[MAXN * 4];
__device__ float g_as2[MAXN], g_ad2[MAXN];
__device__ __align__(16) float g_inv1[MAXN * 4];
__device__ float g_inv2[MAXN];
__device__ __align__(16) float g_exA1[MAXEPN * 4]; // softmax numerators layer1
__device__ float g_exA2[MAXEPN];
__device__ int g_deg[MAXN];
__device__ int g_rowptr[MAXN + 1];
__device__ int g_cursor[MAXN];
__device__ int g_csrc[MAXEPN];                     // CSR: src per (dst-sorted) edge
__device__ int g_bsum[64];                         // scan block sums
__device__ int g_boff[64];

// ---------------- init: zero degree counters --------------------------------
__global__ void init_kernel(int n) {
    int i = blockIdx.x * blockDim.x + threadIdx.x;
    if (i < n) g_deg[i] = 0;
}

// ---------------- CSR build --------------------------------------------------
__global__ void hist_kernel(const int* __restrict__ ei, int E, int n) {
    int idx = blockIdx.x * blockDim.x + threadIdx.x;
    if (idx >= E + n) return;
    int d = (idx < E) ? ei[E + idx] : (idx - E);
    atomicAdd(&g_deg[d], 1);
}

__global__ void scan_local_kernel(int n) {
    __shared__ int wsum[32];
    int lane = threadIdx.x & 31, wid = threadIdx.x >> 5;
    int i = blockIdx.x * 1024 + threadIdx.x;
    int v = (i < n) ? g_deg[i] : 0;
    int x = v;
    #pragma unroll
    for (int o = 1; o < 32; o <<= 1) {
        int y = __shfl_up_sync(0xffffffffu, x, o);
        if (lane >= o) x += y;
    }
    if (lane == 31) wsum[wid] = x;
    __syncthreads();
    if (wid == 0) {
        int w = wsum[lane];
        int xs = w;
        #pragma unroll
        for (int o = 1; o < 32; o <<= 1) {
            int y = __shfl_up_sync(0xffffffffu, xs, o);
            if (lane >= o) xs += y;
        }
        wsum[lane] = xs - w;
    }
    __syncthreads();
    int excl = wsum[wid] + x - v;
    if (i < n) g_rowptr[i] = excl;
    if (threadIdx.x == 1023) g_bsum[blockIdx.x] = excl + v;
}

__global__ void scan_bsum_kernel(int nb) {
    __shared__ int s[64];
    int t = threadIdx.x;
    s[t] = (t < nb) ? g_bsum[t] : 0;
    __syncthreads();
    for (int o = 1; o < 64; o <<= 1) {
        int v = (t >= o) ? s[t - o] : 0;
        __syncthreads();
        s[t] += v;
        __syncthreads();
    }
    int incl = s[t];
    g_boff[t] = incl - ((t < nb) ? g_bsum[t] : 0);
}

__global__ void scan_add_kernel(int n, int total) {
    int i = blockIdx.x * blockDim.x + threadIdx.x;
    if (i < n) {
        int r = g_rowptr[i] + g_boff[i >> 10];
        g_rowptr[i] = r;
        g_cursor[i] = r;
    }
    if (i == 0) g_rowptr[n] = total;
}

__global__ void scatter_kernel(const int* __restrict__ ei, int E, int n) {
    int idx = blockIdx.x * blockDim.x + threadIdx.x;
    if (idx >= E + n) return;
    int s, d;
    if (idx < E) { s = ei[idx]; d = ei[E + idx]; } else { s = d = idx - E; }
    int pos = atomicAdd(&g_cursor[d], 1);
    g_csrc[pos] = s;
}

// ---------------- 3xTF32 tensor-core GEMM -----------------------------------
// C[n,m] = A[n,k] @ B[k,m]; mma.sync m16n8k8 tf32, hi/lo split for fp32 accuracy.
__device__ __forceinline__ void split_tf32(float v, unsigned& hi, unsigned& lo) {
    unsigned h;
    asm("cvt.rna.tf32.f32 %0, %1;" : "=r"(h) : "f"(v));
    float l = v - __uint_as_float(h);
    unsigned lw;
    asm("cvt.rna.tf32.f32 %0, %1;" : "=r"(lw) : "f"(l));
    hi = h; lo = lw;
}

__device__ __forceinline__ void mma_tf32(float& c0, float& c1, float& c2, float& c3,
                                         unsigned a0, unsigned a1, unsigned a2, unsigned a3,
                                         unsigned b0, unsigned b1) {
    asm volatile(
        "mma.sync.aligned.m16n8k8.row.col.f32.tf32.tf32.f32 "
        "{%0,%1,%2,%3},{%4,%5,%6,%7},{%8,%9},{%0,%1,%2,%3};"
        : "+f"(c0), "+f"(c1), "+f"(c2), "+f"(c3)
        : "r"(a0), "r"(a1), "r"(a2), "r"(a3), "r"(b0), "r"(b1));
}

// BM=128 rows, BN columns (128 or 64), BK=16. 256 threads = 8 warps (4 m x 2 n).
template <int BN>
__global__ void gemm_tc_kernel(const float* __restrict__ A, const float* __restrict__ B,
                               float* __restrict__ C, int n, int k, int m) {
    constexpr int BM = 128, BK = 16;
    constexpr int WN = BN / 2;           // warp col tile
    constexpr int NFRAG = WN / 8;        // 8 (BN=128) or 4 (BN=64)
    constexpr int AP = BM + 8;           // smem pads chosen so the 4 tid4-groups
    constexpr int BP = BN + 8;           // land on disjoint bank octets
    constexpr int AITER = BM * BK / 4 / 256;   // 2
    constexpr int BITER = BK * BN / 4 / 256;   // 2 or 1

    __shared__ unsigned Ahi[BK][AP], Alo[BK][AP];
    __shared__ unsigned Bhi[BK][BP], Blo[BK][BP];

    int tid = threadIdx.x;
    int warp = tid >> 5, lane = tid & 31;
    int wm = warp & 3, wn = warp >> 2;
    int g = lane >> 2, t4 = lane & 3;
    int row0 = blockIdx.y * BM, col0 = blockIdx.x * BN;

    float4 aR[AITER], bR[BITER];

    auto loadTile = [&](int kt) {
        #pragma unroll
        for (int i = 0; i < AITER; i++) {
            int slot = tid + i * 256;
            int r = slot / (BK / 4), q = slot % (BK / 4);
            int gr = row0 + r;
            aR[i] = (gr < n)
                ? *reinterpret_cast<const float4*>(&A[(size_t)gr * k + kt + q * 4])
                : make_float4(0.f, 0.f, 0.f, 0.f);
        }
        #pragma unroll
        for (int i = 0; i < BITER; i++) {
            int slot = tid + i * 256;
            int kr = slot / (BN / 4), nc = slot % (BN / 4);
            bR[i] = *reinterpret_cast<const float4*>(&B[(size_t)(kt + kr) * m + col0 + nc * 4]);
        }
    };
    auto storeTile = [&]() {
        #pragma unroll
        for (int i = 0; i < AITER; i++) {
            int slot = tid + i * 256;
            int r = slot / (BK / 4), q = slot % (BK / 4);
            float v[4] = {aR[i].x, aR[i].y, aR[i].z, aR[i].w};
            #pragma unroll
            for (int j = 0; j < 4; j++) {
                unsigned h, l;
                split_tf32(v[j], h, l);
                Ahi[q * 4 + j][r] = h;
                Alo[q * 4 + j][r] = l;
            }
        }
        #pragma unroll
        for (int i = 0; i < BITER; i++) {
            int slot = tid + i * 256;
            int kr = slot / (BN / 4), nc = slot % (BN / 4);
            float v[4] = {bR[i].x, bR[i].y, bR[i].z, bR[i].w};
            #pragma unroll
            for (int j = 0; j < 4; j++) {
                unsigned h, l;
                split_tf32(v[j], h, l);
                Bhi[kr][nc * 4 + j] = h;
                Blo[kr][nc * 4 + j] = l;
            }
        }
    };

    float acc[2][NFRAG][4];
    #pragma unroll
    for (int i = 0; i < 2; i++)
        #pragma unroll
        for (int j = 0; j < NFRAG; j++)
            #pragma unroll
            for (int q = 0; q < 4; q++) acc[i][j][q] = 0.f;

    int tiles = k / BK;
    loadTile(0);
    storeTile();
    __syncthreads();

    for (int t = 0; t < tiles; t++) {
        if (t + 1 < tiles) loadTile((t + 1) * BK);
        #pragma unroll
        for (int ks = 0; ks < BK / 8; ks++) {
            int k0 = ks * 8;
            // A fragments (2 m-frags, hi+lo)
            unsigned ah[2][4], al[2][4];
            #pragma unroll
            for (int mf = 0; mf < 2; mf++) {
                int rb = wm * 32 + mf * 16;
                ah[mf][0] = Ahi[k0 + t4][rb + g];
                ah[mf][1] = Ahi[k0 + t4][rb + g + 8];
                ah[mf][2] = Ahi[k0 + t4 + 4][rb + g];
                ah[mf][3] = Ahi[k0 + t4 + 4][rb + g + 8];
                al[mf][0] = Alo[k0 + t4][rb + g];
                al[mf][1] = Alo[k0 + t4][rb + g + 8];
                al[mf][2] = Alo[k0 + t4 + 4][rb + g];
                al[mf][3] = Alo[k0 + t4 + 4][rb + g + 8];
            }
            // B fragments (NFRAG n-frags, hi+lo)
            unsigned bh[NFRAG][2], bl[NFRAG][2];
            #pragma unroll
            for (int nf = 0; nf < NFRAG; nf++) {
                int cb = wn * WN + nf * 8 + g;
                bh[nf][0] = Bhi[k0 + t4][cb];
                bh[nf][1] = Bhi[k0 + t4 + 4][cb];
                bl[nf][0] = Blo[k0 + t4][cb];
                bl[nf][1] = Blo[k0 + t4 + 4][cb];
            }
            #pragma unroll
            for (int mf = 0; mf < 2; mf++)
                #pragma unroll
                for (int nf = 0; nf < NFRAG; nf++) {
                    float* c = acc[mf][nf];
                    mma_tf32(c[0], c[1], c[2], c[3],
                             ah[mf][0], ah[mf][1], ah[mf][2], ah[mf][3],
                             bh[nf][0], bh[nf][1]);
                    mma_tf32(c[0], c[1], c[2], c[3],
                             ah[mf][0], ah[mf][1], ah[mf][2], ah[mf][3],
                             bl[nf][0], bl[nf][1]);
                    mma_tf32(c[0], c[1], c[2], c[3],
                             al[mf][0], al[mf][1], al[mf][2], al[mf][3],
                             bh[nf][0], bh[nf][1]);
                }
        }
        __syncthreads();
        if (t + 1 < tiles) {
            storeTile();
            __syncthreads();
        }
    }

    // epilogue: c0=C[g][2t4], c1=C[g][2t4+1], c2=C[g+8][2t4], c3=[g+8][2t4+1]
    #pragma unroll
    for (int mf = 0; mf < 2; mf++) {
        int rbase = row0 + wm * 32 + mf * 16;
        #pragma unroll
        for (int nf = 0; nf < NFRAG; nf++) {
            int cb = col0 + wn * WN + nf * 8 + t4 * 2;
            int r0r = rbase + g, r1r = rbase + g + 8;
            if (r0r < n)
                *reinterpret_cast<float2*>(&C[(size_t)r0r * m + cb]) =
                    make_float2(acc[mf][nf][0], acc[mf][nf][1]);
            if (r1r < n)
                *reinterpret_cast<float2*>(&C[(size_t)r1r * m + cb]) =
                    make_float2(acc[mf][nf][2], acc[mf][nf][3]);
        }
    }
}

// ---------------- per-node attention coefficients (one warp / node) ---------
__global__ void alpha_kernel(const float* __restrict__ hm, const float* __restrict__ atts,
                             const float* __restrict__ attd, float* __restrict__ as_,
                             float* __restrict__ ad_, int n, int heads, int c) {
    int gt = blockIdx.x * blockDim.x + threadIdx.x;
    int node = gt >> 5, lane = gt & 31;
    if (node >= n) return;
    for (int h = 0; h < heads; h++) {
        float ss = 0.f, sd = 0.f;
        for (int j = lane; j < c; j += 32) {
            float v = hm[(node * heads + h) * c + j];
            ss += v * atts[h * c + j];
            sd += v * attd[h * c + j];
        }
        #pragma unroll
        for (int o = 16; o; o >>= 1) {
            ss += __shfl_down_sync(0xffffffffu, ss, o);
            sd += __shfl_down_sync(0xffffffffu, sd, o);
        }
        if (lane == 0) { as_[node * heads + h] = ss; ad_[node * heads + h] = sd; }
    }
}

// ---------------- softmax over incoming edges (warp per node) ---------------
template <int H>
__global__ void softmax_kernel(const float* __restrict__ as_, const float* __restrict__ ad_,
                               float* __restrict__ exA, float* __restrict__ invden, int n) {
    int gt = blockIdx.x * blockDim.x + threadIdx.x;
    int node = gt >> 5, lane = gt & 31;
    if (node >= n) return;
    int r0 = g_rowptr[node], r1 = g_rowptr[node + 1];

    float adv[H];
    #pragma unroll
    for (int h = 0; h < H; h++) adv[h] = ad_[node * H + h];

    float mx[H];
    #pragma unroll
    for (int h = 0; h < H; h++) mx[h] = -1e30f;

    for (int j = r0 + lane; j < r1; j += 32) {
        int s = g_csrc[j];
        float ev[H];
        if (H == 4) {
            float4 a4 = reinterpret_cast<const float4*>(as_)[s];
            ev[0] = a4.x; ev[1] = a4.y; ev[2] = a4.z; ev[3] = a4.w;
        } else {
            ev[0] = as_[s];
        }
        #pragma unroll
        for (int h = 0; h < H; h++) {
            float v = ev[h] + adv[h];
            v = (v > 0.f) ? v : 0.2f * v;
            mx[h] = fmaxf(mx[h], v);
        }
    }
    #pragma unroll
    for (int h = 0; h < H; h++)
        #pragma unroll
        for (int o = 16; o; o >>= 1)
            mx[h] = fmaxf(mx[h], __shfl_xor_sync(0xffffffffu, mx[h], o));

    float sum[H];
    #pragma unroll
    for (int h = 0; h < H; h++) sum[h] = 0.f;

    for (int j = r0 + lane; j < r1; j += 32) {
        int s = g_csrc[j];
        float ev[H];
        if (H == 4) {
            float4 a4 = reinterpret_cast<const float4*>(as_)[s];
            ev[0] = a4.x; ev[1] = a4.y; ev[2] = a4.z; ev[3] = a4.w;
        } else {
            ev[0] = as_[s];
        }
        float exv[H];
        #pragma unroll
        for (int h = 0; h < H; h++) {
            float v = ev[h] + adv[h];
            v = (v > 0.f) ? v : 0.2f * v;
            float ex = __expf(v - mx[h]);
            exv[h] = ex;
            sum[h] += ex;
        }
        if (H == 4) {
            reinterpret_cast<float4*>(exA)[j] = make_float4(exv[0], exv[1], exv[2], exv[3]);
        } else {
            exA[j] = exv[0];
        }
    }
    #pragma unroll
    for (int h = 0; h < H; h++)
        #pragma unroll
        for (int o = 16; o; o >>= 1)
            sum[h] += __shfl_xor_sync(0xffffffffu, sum[h], o);

    if (lane == 0) {
        #pragma unroll
        for (int h = 0; h < H; h++)
            invden[node * H + h] = 1.f / (sum[h] + 1e-16f);
    }
}

// ---------------- aggregation layer1: 1 node/block, smem-staged -------------
__global__ void agg1_kernel(const float* __restrict__ exA, const float* __restrict__ invden,
                            const float* __restrict__ hm, const float* __restrict__ bias,
                            float* __restrict__ out, int n) {
    const int CHUNK = 64;
    __shared__ int s_src[CHUNK];
    __shared__ float s_a[CHUNK * 4];
    int tid = threadIdx.x;
    int node = blockIdx.x;
    int ch = tid;
    int h = ch >> 6;
    int r0 = g_rowptr[node], r1 = g_rowptr[node + 1];
    float inv = invden[node * 4 + h];
    float acc = 0.f;
    for (int base = r0; base < r1; base += CHUNK) {
        int cnt = min(CHUNK, r1 - base);
        if (tid < cnt) {
            s_src[tid] = g_csrc[base + tid];
            reinterpret_cast<float4*>(s_a)[tid] = reinterpret_cast<const float4*>(exA)[base + tid];
        }
        __syncthreads();
        #pragma unroll 4
        for (int j = 0; j < cnt; j++) {
            int s = s_src[j];
            acc += hm[(size_t)s * 256 + ch] * s_a[j * 4 + h];
        }
        __syncthreads();
    }
    float r = acc * inv + bias[ch];
    r = (r > 0.f) ? r : (__expf(r) - 1.f);
    out[(size_t)node * 256 + ch] = r;
}

// ---------------- aggregation layer2: 4 nodes/block, direct -----------------
__global__ void agg2_kernel(const float* __restrict__ exA, const float* __restrict__ invden,
                            const float* __restrict__ hm, const float* __restrict__ bias,
                            float* __restrict__ out, int n) {
    int tid = threadIdx.x;
    int node = blockIdx.x * 4 + tid / 64;
    int ch = tid % 64;
    if (node >= n) return;
    int r0 = g_rowptr[node], r1 = g_rowptr[node + 1];
    float inv = invden[node];
    float acc = 0.f;
    #pragma unroll 4
    for (int j = r0; j < r1; j++) {
        int s = g_csrc[j];
        acc += hm[(size_t)s * 64 + ch] * exA[j];
    }
    out[(size_t)node * 64 + ch] = acc * inv + bias[ch];
}

// ---------------- launch ----------------------------------------------------
extern "C" void kernel_launch(void* const* d_in, const int* in_sizes, int n_in,
                              void* d_out, int out_size) {
    const float* x   = (const float*)d_in[0];
    const int*   ei  = (const int*)d_in[1];
    const float* W1  = (const float*)d_in[2];
    const float* a1s = (const float*)d_in[3];
    const float* a1d = (const float*)d_in[4];
    const float* b1  = (const float*)d_in[5];
    const float* W2  = (const float*)d_in[6];
    const float* a2s = (const float*)d_in[7];
    const float* a2d = (const float*)d_in[8];
    const float* b2  = (const float*)d_in[9];
    float* out = (float*)d_out;

    int N = in_sizes[0] / 128;
    int E = in_sizes[1] / 2;
    int EPN = E + N;
    int NB = (N + 1023) / 1024;

    float *h1, *out1, *h2, *as1, *ad1, *as2, *ad2, *inv1, *inv2, *exA1, *exA2;
    cudaGetSymbolAddress((void**)&h1,   g_h1);
    cudaGetSymbolAddress((void**)&out1, g_out1);
    cudaGetSymbolAddress((void**)&h2,   g_h2);
    cudaGetSymbolAddress((void**)&as1,  g_as1);
    cudaGetSymbolAddress((void**)&ad1,  g_ad1);
    cudaGetSymbolAddress((void**)&as2,  g_as2);
    cudaGetSymbolAddress((void**)&ad2,  g_ad2);
    cudaGetSymbolAddress((void**)&inv1, g_inv1);
    cudaGetSymbolAddress((void**)&inv2, g_inv2);
    cudaGetSymbolAddress((void**)&exA1, g_exA1);
    cudaGetSymbolAddress((void**)&exA2, g_exA2);

    // CSR build (shared by both layers)
    init_kernel<<<(N + 255) / 256, 256>>>(N);
    hist_kernel<<<(EPN + 255) / 256, 256>>>(ei, E, N);
    scan_local_kernel<<<NB, 1024>>>(N);
    scan_bsum_kernel<<<1, 64>>>(NB);
    scan_add_kernel<<<(N + 255) / 256, 256>>>(N, EPN);
    scatter_kernel<<<(EPN + 255) / 256, 256>>>(ei, E, N);

    // ---- layer 1 ----
    gemm_tc_kernel<128><<<dim3(2, (N + 127) / 128), 256>>>(x, W1, h1, N, 128, 256);
    alpha_kernel<<<(N * 32 + 255) / 256, 256>>>(h1, a1s, a1d, as1, ad1, N, 4, 64);
    softmax_kernel<4><<<(N * 32 + 255) / 256, 256>>>(as1, ad1, exA1, inv1, N);
    agg1_kernel<<<N, 256>>>(exA1, inv1, h1, b1, out1, N);

    // ---- layer 2 ----
    gemm_tc_kernel<64><<<dim3(1, (N + 127) / 128), 256>>>(out1, W2, h2, N, 256, 64);
    alpha_kernel<<<(N * 32 + 255) / 256, 256>>>(h2, a2s, a2d, as2, ad2, N, 1, 64);
    softmax_kernel<1><<<(N * 32 + 255) / 256, 256>>>(as2, ad2, exA2, inv2, N);
    agg2_kernel<<<(N + 3) / 4, 256>>>(exA2, inv2, h2, b2, out, N);
}

// round 6
// speedup vs baseline: 4.3420x; 1.1183x over previous
#include <cuda_runtime.h>
#include <math.h>

#define MAXN 50000
#define MAXE 800000
#define MAXEPN (MAXE + MAXN)

// ---------------- scratch (device globals) ----------------------------------
__device__ __align__(16) float g_h1[MAXN * 256];   // layer1 GEMM output [N,4,64]
__device__ __align__(16) float g_out1[MAXN * 256]; // layer1 aggregated+elu
__device__ __align__(16) float g_h2[MAXN * 64];    // layer2 GEMM output
__device__ __align__(16) float g_as1[MAXN * 4], g_ad1[MAXN * 4];
__device__ float g_as2[MAXN], g_ad2[MAXN];
__device__ int g_deg[MAXN];
__device__ int g_rowptr[MAXN + 1];
__device__ int g_cursor[MAXN];
__device__ int g_csrc[MAXEPN];                     // CSR: src per (dst-sorted) edge
__device__ int g_bsum[64];
__device__ int g_boff[64];

// ---------------- init: zero deg + layer2 alpha accumulators ----------------
__global__ void init_kernel(int n) {
    int i = blockIdx.x * blockDim.x + threadIdx.x;
    if (i < n) { g_deg[i] = 0; g_as2[i] = 0.f; g_ad2[i] = 0.f; }
}

// ---------------- CSR build --------------------------------------------------
__global__ void hist_kernel(const int* __restrict__ ei, int E, int n) {
    int idx = blockIdx.x * blockDim.x + threadIdx.x;
    if (idx >= E + n) return;
    int d = (idx < E) ? ei[E + idx] : (idx - E);
    atomicAdd(&g_deg[d], 1);
}

__global__ void scan_local_kernel(int n) {
    __shared__ int wsum[32];
    int lane = threadIdx.x & 31, wid = threadIdx.x >> 5;
    int i = blockIdx.x * 1024 + threadIdx.x;
    int v = (i < n) ? g_deg[i] : 0;
    int x = v;
    #pragma unroll
    for (int o = 1; o < 32; o <<= 1) {
        int y = __shfl_up_sync(0xffffffffu, x, o);
        if (lane >= o) x += y;
    }
    if (lane == 31) wsum[wid] = x;
    __syncthreads();
    if (wid == 0) {
        int w = wsum[lane];
        int xs = w;
        #pragma unroll
        for (int o = 1; o < 32; o <<= 1) {
            int y = __shfl_up_sync(0xffffffffu, xs, o);
            if (lane >= o) xs += y;
        }
        wsum[lane] = xs - w;
    }
    __syncthreads();
    int excl = wsum[wid] + x - v;
    if (i < n) g_rowptr[i] = excl;
    if (threadIdx.x == 1023) g_bsum[blockIdx.x] = excl + v;
}

__global__ void scan_bsum_kernel(int nb) {
    __shared__ int s[64];
    int t = threadIdx.x;
    s[t] = (t < nb) ? g_bsum[t] : 0;
    __syncthreads();
    for (int o = 1; o < 64; o <<= 1) {
        int v = (t >= o) ? s[t - o] : 0;
        __syncthreads();
        s[t] += v;
        __syncthreads();
    }
    int incl = s[t];
    g_boff[t] = incl - ((t < nb) ? g_bsum[t] : 0);
}

__global__ void scan_add_kernel(int n, int total) {
    int i = blockIdx.x * blockDim.x + threadIdx.x;
    if (i < n) {
        int r = g_rowptr[i] + g_boff[i >> 10];
        g_rowptr[i] = r;
        g_cursor[i] = r;
    }
    if (i == 0) g_rowptr[n] = total;
}

__global__ void scatter_kernel(const int* __restrict__ ei, int E, int n) {
    int idx = blockIdx.x * blockDim.x + threadIdx.x;
    if (idx >= E + n) return;
    int s, d;
    if (idx < E) { s = ei[idx]; d = ei[E + idx]; } else { s = d = idx - E; }
    int pos = atomicAdd(&g_cursor[d], 1);
    g_csrc[pos] = s;
}

// ---------------- 3xTF32 tensor-core GEMM + fused alpha epilogue ------------
__device__ __forceinline__ void split_tf32(float v, unsigned& hi, unsigned& lo) {
    unsigned h;
    asm("cvt.rna.tf32.f32 %0, %1;" : "=r"(h) : "f"(v));
    float l = v - __uint_as_float(h);
    unsigned lw;
    asm("cvt.rna.tf32.f32 %0, %1;" : "=r"(lw) : "f"(l));
    hi = h; lo = lw;
}

__device__ __forceinline__ void mma_tf32(float& c0, float& c1, float& c2, float& c3,
                                         unsigned a0, unsigned a1, unsigned a2, unsigned a3,
                                         unsigned b0, unsigned b1) {
    asm volatile(
        "mma.sync.aligned.m16n8k8.row.col.f32.tf32.tf32.f32 "
        "{%0,%1,%2,%3},{%4,%5,%6,%7},{%8,%9},{%0,%1,%2,%3};"
        : "+f"(c0), "+f"(c1), "+f"(c2), "+f"(c3)
        : "r"(a0), "r"(a1), "r"(a2), "r"(a3), "r"(b0), "r"(b1));
}

// BM=128, BN columns (128 or 64), BK=16. 256 threads = 8 warps (4 m x 2 n).
// Fused alpha epilogue: per-row dot of the C tile with att_src/att_dst.
// ATOMIC=false (BN=128): each warp's 64-col span == one head; direct store.
// ATOMIC=true  (BN=64): warp covers half the single head; atomicAdd.
template <int BN, bool ATOMIC>
__global__ void gemm_tc_kernel(const float* __restrict__ A, const float* __restrict__ B,
                               float* __restrict__ C, int n, int k, int m,
                               const float* __restrict__ attS, const float* __restrict__ attD,
                               float* __restrict__ asOut, float* __restrict__ adOut) {
    constexpr int BM = 128, BK = 16;
    constexpr int WN = BN / 2;
    constexpr int NFRAG = WN / 8;
    constexpr int AP = BM + 8;
    constexpr int BP = BN + 8;
    constexpr int AITER = BM * BK / 4 / 256;
    constexpr int BITER = BK * BN / 4 / 256;

    __shared__ unsigned Ahi[BK][AP], Alo[BK][AP];
    __shared__ unsigned Bhi[BK][BP], Blo[BK][BP];

    int tid = threadIdx.x;
    int warp = tid >> 5, lane = tid & 31;
    int wm = warp & 3, wn = warp >> 2;
    int g = lane >> 2, t4 = lane & 3;
    int row0 = blockIdx.y * BM, col0 = blockIdx.x * BN;

    float4 aR[AITER], bR[BITER];

    auto loadTile = [&](int kt) {
        #pragma unroll
        for (int i = 0; i < AITER; i++) {
            int slot = tid + i * 256;
            int r = slot / (BK / 4), q = slot % (BK / 4);
            int gr = row0 + r;
            aR[i] = (gr < n)
                ? *reinterpret_cast<const float4*>(&A[(size_t)gr * k + kt + q * 4])
                : make_float4(0.f, 0.f, 0.f, 0.f);
        }
        #pragma unroll
        for (int i = 0; i < BITER; i++) {
            int slot = tid + i * 256;
            int kr = slot / (BN / 4), nc = slot % (BN / 4);
            bR[i] = *reinterpret_cast<const float4*>(&B[(size_t)(kt + kr) * m + col0 + nc * 4]);
        }
    };
    auto storeTile = [&]() {
        #pragma unroll
        for (int i = 0; i < AITER; i++) {
            int slot = tid + i * 256;
            int r = slot / (BK / 4), q = slot % (BK / 4);
            float v[4] = {aR[i].x, aR[i].y, aR[i].z, aR[i].w};
            #pragma unroll
            for (int j = 0; j < 4; j++) {
                unsigned h, l;
                split_tf32(v[j], h, l);
                Ahi[q * 4 + j][r] = h;
                Alo[q * 4 + j][r] = l;
            }
        }
        #pragma unroll
        for (int i = 0; i < BITER; i++) {
            int slot = tid + i * 256;
            int kr = slot / (BN / 4), nc = slot % (BN / 4);
            float v[4] = {bR[i].x, bR[i].y, bR[i].z, bR[i].w};
            #pragma unroll
            for (int j = 0; j < 4; j++) {
                unsigned h, l;
                split_tf32(v[j], h, l);
                Bhi[kr][nc * 4 + j] = h;
                Blo[kr][nc * 4 + j] = l;
            }
        }
    };

    float acc[2][NFRAG][4];
    #pragma unroll
    for (int i = 0; i < 2; i++)
        #pragma unroll
        for (int j = 0; j < NFRAG; j++)
            #pragma unroll
            for (int q = 0; q < 4; q++) acc[i][j][q] = 0.f;

    int tiles = k / BK;
    loadTile(0);
    storeTile();
    __syncthreads();

    for (int t = 0; t < tiles; t++) {
        if (t + 1 < tiles) loadTile((t + 1) * BK);
        #pragma unroll
        for (int ks = 0; ks < BK / 8; ks++) {
            int k0 = ks * 8;
            unsigned ah[2][4], al[2][4];
            #pragma unroll
            for (int mf = 0; mf < 2; mf++) {
                int rb = wm * 32 + mf * 16;
                ah[mf][0] = Ahi[k0 + t4][rb + g];
                ah[mf][1] = Ahi[k0 + t4][rb + g + 8];
                ah[mf][2] = Ahi[k0 + t4 + 4][rb + g];
                ah[mf][3] = Ahi[k0 + t4 + 4][rb + g + 8];
                al[mf][0] = Alo[k0 + t4][rb + g];
                al[mf][1] = Alo[k0 + t4][rb + g + 8];
                al[mf][2] = Alo[k0 + t4 + 4][rb + g];
                al[mf][3] = Alo[k0 + t4 + 4][rb + g + 8];
            }
            unsigned bh[NFRAG][2], bl[NFRAG][2];
            #pragma unroll
            for (int nf = 0; nf < NFRAG; nf++) {
                int cb = wn * WN + nf * 8 + g;
                bh[nf][0] = Bhi[k0 + t4][cb];
                bh[nf][1] = Bhi[k0 + t4 + 4][cb];
                bl[nf][0] = Blo[k0 + t4][cb];
                bl[nf][1] = Blo[k0 + t4 + 4][cb];
            }
            #pragma unroll
            for (int mf = 0; mf < 2; mf++)
                #pragma unroll
                for (int nf = 0; nf < NFRAG; nf++) {
                    float* c = acc[mf][nf];
                    mma_tf32(c[0], c[1], c[2], c[3],
                             ah[mf][0], ah[mf][1], ah[mf][2], ah[mf][3],
                             bh[nf][0], bh[nf][1]);
                    mma_tf32(c[0], c[1], c[2], c[3],
                             ah[mf][0], ah[mf][1], ah[mf][2], ah[mf][3],
                             bl[nf][0], bl[nf][1]);
                    mma_tf32(c[0], c[1], c[2], c[3],
                             al[mf][0], al[mf][1], al[mf][2], al[mf][3],
                             bh[nf][0], bh[nf][1]);
                }
        }
        __syncthreads();
        if (t + 1 < tiles) {
            storeTile();
            __syncthreads();
        }
    }

    // ---- write C tile ----
    #pragma unroll
    for (int mf = 0; mf < 2; mf++) {
        int rbase = row0 + wm * 32 + mf * 16;
        #pragma unroll
        for (int nf = 0; nf < NFRAG; nf++) {
            int cb = col0 + wn * WN + nf * 8 + t4 * 2;
            int r0r = rbase + g, r1r = rbase + g + 8;
            if (r0r < n)
                *reinterpret_cast<float2*>(&C[(size_t)r0r * m + cb]) =
                    make_float2(acc[mf][nf][0], acc[mf][nf][1]);
            if (r1r < n)
                *reinterpret_cast<float2*>(&C[(size_t)r1r * m + cb]) =
                    make_float2(acc[mf][nf][2], acc[mf][nf][3]);
        }
    }

    // ---- fused alpha epilogue ----
    {
        float aSv[NFRAG][2], aDv[NFRAG][2];
        int hsel = ATOMIC ? 0 : ((col0 + wn * WN) >> 6);
        #pragma unroll
        for (int nf = 0; nf < NFRAG; nf++) {
            int idx = (ATOMIC ? wn * WN : 0) + nf * 8 + t4 * 2;
            const float* aS = attS + hsel * 64;
            const float* aD = attD + hsel * 64;
            aSv[nf][0] = aS[idx];     aSv[nf][1] = aS[idx + 1];
            aDv[nf][0] = aD[idx];     aDv[nf][1] = aD[idx + 1];
        }
        #pragma unroll
        for (int mf = 0; mf < 2; mf++) {
            float ds0 = 0.f, dd0 = 0.f, ds1 = 0.f, dd1 = 0.f;
            #pragma unroll
            for (int nf = 0; nf < NFRAG; nf++) {
                ds0 += acc[mf][nf][0] * aSv[nf][0] + acc[mf][nf][1] * aSv[nf][1];
                dd0 += acc[mf][nf][0] * aDv[nf][0] + acc[mf][nf][1] * aDv[nf][1];
                ds1 += acc[mf][nf][2] * aSv[nf][0] + acc[mf][nf][3] * aSv[nf][1];
                dd1 += acc[mf][nf][2] * aDv[nf][0] + acc[mf][nf][3] * aDv[nf][1];
            }
            #pragma unroll
            for (int o = 1; o <= 2; o <<= 1) {
                ds0 += __shfl_xor_sync(0xffffffffu, ds0, o);
                dd0 += __shfl_xor_sync(0xffffffffu, dd0, o);
                ds1 += __shfl_xor_sync(0xffffffffu, ds1, o);
                dd1 += __shfl_xor_sync(0xffffffffu, dd1, o);
            }
            if (t4 == 0) {
                int rbase = row0 + wm * 32 + mf * 16;
                int r0r = rbase + g, r1r = rbase + g + 8;
                if (ATOMIC) {
                    if (r0r < n) { atomicAdd(&asOut[r0r], ds0); atomicAdd(&adOut[r0r], dd0); }
                    if (r1r < n) { atomicAdd(&asOut[r1r], ds1); atomicAdd(&adOut[r1r], dd1); }
                } else {
                    if (r0r < n) { asOut[r0r * 4 + hsel] = ds0; adOut[r0r * 4 + hsel] = dd0; }
                    if (r1r < n) { asOut[r1r * 4 + hsel] = ds1; adOut[r1r * 4 + hsel] = dd1; }
                }
            }
        }
    }
}

// ---------------- fused softmax + aggregation, layer 1 ----------------------
// One node per 256-thread block; 256 channels (4 heads x 64).
__global__ void agg1_kernel(const float* __restrict__ as1, const float* __restrict__ ad1,
                            const float* __restrict__ hm, const float* __restrict__ bias,
                            float* __restrict__ out, int n) {
    const int CHUNK = 64;
    __shared__ int s_src[CHUNK];
    __shared__ float s_w[CHUNK * 4];
    int tid = threadIdx.x;
    int node = blockIdx.x;
    int ch = tid, h = ch >> 6;
    int r0 = g_rowptr[node], r1 = g_rowptr[node + 1];
    float4 adv = reinterpret_cast<const float4*>(ad1)[node];
    float acc = 0.f, dsum = 0.f;
    for (int base = r0; base < r1; base += CHUNK) {
        int cnt = min(CHUNK, r1 - base);
        if (tid < cnt) {
            int s = g_csrc[base + tid];
            s_src[tid] = s;
            float4 a4 = reinterpret_cast<const float4*>(as1)[s];
            float e0 = a4.x + adv.x; e0 = (e0 > 0.f) ? e0 : 0.2f * e0;
            float e1 = a4.y + adv.y; e1 = (e1 > 0.f) ? e1 : 0.2f * e1;
            float e2 = a4.z + adv.z; e2 = (e2 > 0.f) ? e2 : 0.2f * e2;
            float e3 = a4.w + adv.w; e3 = (e3 > 0.f) ? e3 : 0.2f * e3;
            reinterpret_cast<float4*>(s_w)[tid] =
                make_float4(__expf(e0), __expf(e1), __expf(e2), __expf(e3));
        }
        __syncthreads();
        #pragma unroll 4
        for (int j = 0; j < cnt; j++) {
            float w = s_w[j * 4 + h];
            acc += hm[(size_t)s_src[j] * 256 + ch] * w;
            dsum += w;
        }
        __syncthreads();
    }
    float r = acc / (dsum + 1e-16f) + bias[ch];
    r = (r > 0.f) ? r : (__expf(r) - 1.f);
    out[(size_t)node * 256 + ch] = r;
}

// ---------------- fused softmax + aggregation, layer 2 ----------------------
// Two nodes per 128-thread block; 64 channels each, 1 head.
__global__ void agg2_kernel(const float* __restrict__ as2, const float* __restrict__ ad2,
                            const float* __restrict__ hm, const float* __restrict__ bias,
                            float* __restrict__ out, int n) {
    const int CHUNK = 64;
    __shared__ int s_src[2][CHUNK];
    __shared__ float s_w[2][CHUNK];
    int tid = threadIdx.x;
    int sub = tid >> 6;          // 0 or 1: which node in this block
    int ch = tid & 63;
    int node = blockIdx.x * 2 + sub;
    bool active = (node < n);
    int r0 = 0, r1 = 0;
    float adv = 0.f;
    if (active) {
        r0 = g_rowptr[node];
        r1 = g_rowptr[node + 1];
        adv = ad2[node];
    }
    int deg = r1 - r0;
    // max chunks across both nodes so __syncthreads stays uniform
    __shared__ int s_maxdeg;
    if (tid == 0) s_maxdeg = 0;
    __syncthreads();
    if (ch == 0 && active) atomicMax(&s_maxdeg, deg);
    __syncthreads();
    int rounds = (s_maxdeg + CHUNK - 1) / CHUNK;

    float acc = 0.f, dsum = 0.f;
    for (int rIt = 0; rIt < rounds; rIt++) {
        int base = r0 + rIt * CHUNK;
        int cnt = active ? min(CHUNK, r1 - base) : 0;
        if (cnt < 0) cnt = 0;
        if (ch < cnt) {
            int s = g_csrc[base + ch];
            s_src[sub][ch] = s;
            float e = as2[s] + adv;
            e = (e > 0.f) ? e : 0.2f * e;
            s_w[sub][ch] = __expf(e);
        }
        __syncthreads();
        #pragma unroll 4
        for (int j = 0; j < cnt; j++) {
            float w = s_w[sub][j];
            acc += hm[(size_t)s_src[sub][j] * 64 + ch] * w;
            dsum += w;
        }
        __syncthreads();
    }
    if (active)
        out[(size_t)node * 64 + ch] = acc / (dsum + 1e-16f) + bias[ch];
}

// ---------------- launch ----------------------------------------------------
extern "C" void kernel_launch(void* const* d_in, const int* in_sizes, int n_in,
                              void* d_out, int out_size) {
    const float* x   = (const float*)d_in[0];
    const int*   ei  = (const int*)d_in[1];
    const float* W1  = (const float*)d_in[2];
    const float* a1s = (const float*)d_in[3];
    const float* a1d = (const float*)d_in[4];
    const float* b1  = (const float*)d_in[5];
    const float* W2  = (const float*)d_in[6];
    const float* a2s = (const float*)d_in[7];
    const float* a2d = (const float*)d_in[8];
    const float* b2  = (const float*)d_in[9];
    float* out = (float*)d_out;

    int N = in_sizes[0] / 128;
    int E = in_sizes[1] / 2;
    int EPN = E + N;
    int NB = (N + 1023) / 1024;

    float *h1, *out1, *h2, *as1, *ad1, *as2, *ad2;
    cudaGetSymbolAddress((void**)&h1,   g_h1);
    cudaGetSymbolAddress((void**)&out1, g_out1);
    cudaGetSymbolAddress((void**)&h2,   g_h2);
    cudaGetSymbolAddress((void**)&as1,  g_as1);
    cudaGetSymbolAddress((void**)&ad1,  g_ad1);
    cudaGetSymbolAddress((void**)&as2,  g_as2);
    cudaGetSymbolAddress((void**)&ad2,  g_ad2);

    // CSR build (shared by both layers) + zero of layer2 alpha accumulators
    init_kernel<<<(N + 255) / 256, 256>>>(N);
    hist_kernel<<<(EPN + 255) / 256, 256>>>(ei, E, N);
    scan_local_kernel<<<NB, 1024>>>(N);
    scan_bsum_kernel<<<1, 64>>>(NB);
    scan_add_kernel<<<(N + 255) / 256, 256>>>(N, EPN);
    scatter_kernel<<<(EPN + 255) / 256, 256>>>(ei, E, N);

    // ---- layer 1: GEMM(+alpha) -> fused softmax+agg(+bias+ELU) ----
    gemm_tc_kernel<128, false><<<dim3(2, (N + 127) / 128), 256>>>(
        x, W1, h1, N, 128, 256, a1s, a1d, as1, ad1);
    agg1_kernel<<<N, 256>>>(as1, ad1, h1, b1, out1, N);

    // ---- layer 2: GEMM(+alpha atomic) -> fused softmax+agg(+bias) ----
    gemm_tc_kernel<64, true><<<dim3(1, (N + 127) / 128), 256>>>(
        out1, W2, h2, N, 256, 64, a2s, a2d, as2, ad2);
    agg2_kernel<<<(N + 1) / 2, 128>>>(as2, ad2, h2, b2, out, N);
}

// round 8
// speedup vs baseline: 5.6504x; 1.3013x over previous
#include <cuda_runtime.h>
#include <math.h>

#define MAXN 50000
#define MAXE 800000
#define MAXEPN (MAXE + MAXN)

// ---------------- scratch (device globals) ----------------------------------
__device__ __align__(16) float g_h1[MAXN * 256];   // layer1 GEMM output [N,4,64]
__device__ __align__(16) float g_out1[MAXN * 256]; // layer1 aggregated+elu
__device__ __align__(16) float g_h2[MAXN * 64];    // layer2 GEMM output
__device__ __align__(16) float g_as1[MAXN * 4], g_ad1[MAXN * 4];
__device__ float g_as2[MAXN], g_ad2[MAXN];
__device__ int g_deg[MAXN];
__device__ int g_rowptr[MAXN + 1];
__device__ int g_cursor[MAXN];
__device__ int g_csrc[MAXEPN];                     // CSR: src per (dst-sorted) edge
__device__ int g_bsum[64];
__device__ int g_boff[64];

// ---------------- init: zero deg + layer2 alpha accumulators ----------------
__global__ void init_kernel(int n) {
    int i = blockIdx.x * blockDim.x + threadIdx.x;
    if (i < n) { g_deg[i] = 0; g_as2[i] = 0.f; g_ad2[i] = 0.f; }
}

// ---------------- CSR build --------------------------------------------------
__global__ void hist_kernel(const int* __restrict__ ei, int E, int n) {
    int idx = blockIdx.x * blockDim.x + threadIdx.x;
    if (idx >= E + n) return;
    int d = (idx < E) ? ei[E + idx] : (idx - E);
    atomicAdd(&g_deg[d], 1);
}

__global__ void scan_local_kernel(int n) {
    __shared__ int wsum[32];
    int lane = threadIdx.x & 31, wid = threadIdx.x >> 5;
    int i = blockIdx.x * 1024 + threadIdx.x;
    int v = (i < n) ? g_deg[i] : 0;
    int x = v;
    #pragma unroll
    for (int o = 1; o < 32; o <<= 1) {
        int y = __shfl_up_sync(0xffffffffu, x, o);
        if (lane >= o) x += y;
    }
    if (lane == 31) wsum[wid] = x;
    __syncthreads();
    if (wid == 0) {
        int w = wsum[lane];
        int xs = w;
        #pragma unroll
        for (int o = 1; o < 32; o <<= 1) {
            int y = __shfl_up_sync(0xffffffffu, xs, o);
            if (lane >= o) xs += y;
        }
        wsum[lane] = xs - w;
    }
    __syncthreads();
    int excl = wsum[wid] + x - v;
    if (i < n) g_rowptr[i] = excl;
    if (threadIdx.x == 1023) g_bsum[blockIdx.x] = excl + v;
}

__global__ void scan_bsum_kernel(int nb) {
    __shared__ int s[64];
    int t = threadIdx.x;
    s[t] = (t < nb) ? g_bsum[t] : 0;
    __syncthreads();
    for (int o = 1; o < 64; o <<= 1) {
        int v = (t >= o) ? s[t - o] : 0;
        __syncthreads();
        s[t] += v;
        __syncthreads();
    }
    int incl = s[t];
    g_boff[t] = incl - ((t < nb) ? g_bsum[t] : 0);
}

__global__ void scan_add_kernel(int n, int total) {
    int i = blockIdx.x * blockDim.x + threadIdx.x;
    if (i < n) {
        int r = g_rowptr[i] + g_boff[i >> 10];
        g_rowptr[i] = r;
        g_cursor[i] = r;
    }
    if (i == 0) g_rowptr[n] = total;
}

__global__ void scatter_kernel(const int* __restrict__ ei, int E, int n) {
    int idx = blockIdx.x * blockDim.x + threadIdx.x;
    if (idx >= E + n) return;
    int s, d;
    if (idx < E) { s = ei[idx]; d = ei[E + idx]; } else { s = d = idx - E; }
    int pos = atomicAdd(&g_cursor[d], 1);
    g_csrc[pos] = s;
}

// ---------------- 3xTF32 tensor-core GEMM + fused alpha epilogue ------------
__device__ __forceinline__ void split_tf32(float v, unsigned& hi, unsigned& lo) {
    unsigned h;
    asm("cvt.rna.tf32.f32 %0, %1;" : "=r"(h) : "f"(v));
    float l = v - __uint_as_float(h);
    unsigned lw;
    asm("cvt.rna.tf32.f32 %0, %1;" : "=r"(lw) : "f"(l));
    hi = h; lo = lw;
}

__device__ __forceinline__ void mma_tf32(float& c0, float& c1, float& c2, float& c3,
                                         unsigned a0, unsigned a1, unsigned a2, unsigned a3,
                                         unsigned b0, unsigned b1) {
    asm volatile(
        "mma.sync.aligned.m16n8k8.row.col.f32.tf32.tf32.f32 "
        "{%0,%1,%2,%3},{%4,%5,%6,%7},{%8,%9},{%0,%1,%2,%3};"
        : "+f"(c0), "+f"(c1), "+f"(c2), "+f"(c3)
        : "r"(a0), "r"(a1), "r"(a2), "r"(a3), "r"(b0), "r"(b1));
}

// BM=128, BN columns (128 or 64), BK=16. 256 threads = 8 warps (4 m x 2 n).
template <int BN, bool ATOMIC>
__global__ void gemm_tc_kernel(const float* __restrict__ A, const float* __restrict__ B,
                               float* __restrict__ C, int n, int k, int m,
                               const float* __restrict__ attS, const float* __restrict__ attD,
                               float* __restrict__ asOut, float* __restrict__ adOut) {
    constexpr int BM = 128, BK = 16;
    constexpr int WN = BN / 2;
    constexpr int NFRAG = WN / 8;
    constexpr int AP = BM + 8;
    constexpr int BP = BN + 8;
    constexpr int AITER = BM * BK / 4 / 256;
    constexpr int BITER = BK * BN / 4 / 256;

    __shared__ unsigned Ahi[BK][AP], Alo[BK][AP];
    __shared__ unsigned Bhi[BK][BP], Blo[BK][BP];

    int tid = threadIdx.x;
    int warp = tid >> 5, lane = tid & 31;
    int wm = warp & 3, wn = warp >> 2;
    int g = lane >> 2, t4 = lane & 3;
    int row0 = blockIdx.y * BM, col0 = blockIdx.x * BN;

    float4 aR[AITER], bR[BITER];

    auto loadTile = [&](int kt) {
        #pragma unroll
        for (int i = 0; i < AITER; i++) {
            int slot = tid + i * 256;
            int r = slot / (BK / 4), q = slot % (BK / 4);
            int gr = row0 + r;
            aR[i] = (gr < n)
                ? *reinterpret_cast<const float4*>(&A[(size_t)gr * k + kt + q * 4])
                : make_float4(0.f, 0.f, 0.f, 0.f);
        }
        #pragma unroll
        for (int i = 0; i < BITER; i++) {
            int slot = tid + i * 256;
            int kr = slot / (BN / 4), nc = slot % (BN / 4);
            bR[i] = *reinterpret_cast<const float4*>(&B[(size_t)(kt + kr) * m + col0 + nc * 4]);
        }
    };
    auto storeTile = [&]() {
        #pragma unroll
        for (int i = 0; i < AITER; i++) {
            int slot = tid + i * 256;
            int r = slot / (BK / 4), q = slot % (BK / 4);
            float v[4] = {aR[i].x, aR[i].y, aR[i].z, aR[i].w};
            #pragma unroll
            for (int j = 0; j < 4; j++) {
                unsigned h, l;
                split_tf32(v[j], h, l);
                Ahi[q * 4 + j][r] = h;
                Alo[q * 4 + j][r] = l;
            }
        }
        #pragma unroll
        for (int i = 0; i < BITER; i++) {
            int slot = tid + i * 256;
            int kr = slot / (BN / 4), nc = slot % (BN / 4);
            float v[4] = {bR[i].x, bR[i].y, bR[i].z, bR[i].w};
            #pragma unroll
            for (int j = 0; j < 4; j++) {
                unsigned h, l;
                split_tf32(v[j], h, l);
                Bhi[kr][nc * 4 + j] = h;
                Blo[kr][nc * 4 + j] = l;
            }
        }
    };

    float acc[2][NFRAG][4];
    #pragma unroll
    for (int i = 0; i < 2; i++)
        #pragma unroll
        for (int j = 0; j < NFRAG; j++)
            #pragma unroll
            for (int q = 0; q < 4; q++) acc[i][j][q] = 0.f;

    int tiles = k / BK;
    loadTile(0);
    storeTile();
    __syncthreads();

    for (int t = 0; t < tiles; t++) {
        if (t + 1 < tiles) loadTile((t + 1) * BK);
        #pragma unroll
        for (int ks = 0; ks < BK / 8; ks++) {
            int k0 = ks * 8;
            unsigned ah[2][4], al[2][4];
            #pragma unroll
            for (int mf = 0; mf < 2; mf++) {
                int rb = wm * 32 + mf * 16;
                ah[mf][0] = Ahi[k0 + t4][rb + g];
                ah[mf][1] = Ahi[k0 + t4][rb + g + 8];
                ah[mf][2] = Ahi[k0 + t4 + 4][rb + g];
                ah[mf][3] = Ahi[k0 + t4 + 4][rb + g + 8];
                al[mf][0] = Alo[k0 + t4][rb + g];
                al[mf][1] = Alo[k0 + t4][rb + g + 8];
                al[mf][2] = Alo[k0 + t4 + 4][rb + g];
                al[mf][3] = Alo[k0 + t4 + 4][rb + g + 8];
            }
            unsigned bh[NFRAG][2], bl[NFRAG][2];
            #pragma unroll
            for (int nf = 0; nf < NFRAG; nf++) {
                int cb = wn * WN + nf * 8 + g;
                bh[nf][0] = Bhi[k0 + t4][cb];
                bh[nf][1] = Bhi[k0 + t4 + 4][cb];
                bl[nf][0] = Blo[k0 + t4][cb];
                bl[nf][1] = Blo[k0 + t4 + 4][cb];
            }
            #pragma unroll
            for (int mf = 0; mf < 2; mf++)
                #pragma unroll
                for (int nf = 0; nf < NFRAG; nf++) {
                    float* c = acc[mf][nf];
                    mma_tf32(c[0], c[1], c[2], c[3],
                             ah[mf][0], ah[mf][1], ah[mf][2], ah[mf][3],
                             bh[nf][0], bh[nf][1]);
                    mma_tf32(c[0], c[1], c[2], c[3],
                             ah[mf][0], ah[mf][1], ah[mf][2], ah[mf][3],
                             bl[nf][0], bl[nf][1]);
                    mma_tf32(c[0], c[1], c[2], c[3],
                             al[mf][0], al[mf][1], al[mf][2], al[mf][3],
                             bh[nf][0], bh[nf][1]);
                }
        }
        __syncthreads();
        if (t + 1 < tiles) {
            storeTile();
            __syncthreads();
        }
    }

    // ---- write C tile ----
    #pragma unroll
    for (int mf = 0; mf < 2; mf++) {
        int rbase = row0 + wm * 32 + mf * 16;
        #pragma unroll
        for (int nf = 0; nf < NFRAG; nf++) {
            int cb = col0 + wn * WN + nf * 8 + t4 * 2;
            int r0r = rbase + g, r1r = rbase + g + 8;
            if (r0r < n)
                *reinterpret_cast<float2*>(&C[(size_t)r0r * m + cb]) =
                    make_float2(acc[mf][nf][0], acc[mf][nf][1]);
            if (r1r < n)
                *reinterpret_cast<float2*>(&C[(size_t)r1r * m + cb]) =
                    make_float2(acc[mf][nf][2], acc[mf][nf][3]);
        }
    }

    // ---- fused alpha epilogue ----
    {
        float aSv[NFRAG][2], aDv[NFRAG][2];
        int hsel = ATOMIC ? 0 : ((col0 + wn * WN) >> 6);
        #pragma unroll
        for (int nf = 0; nf < NFRAG; nf++) {
            int idx = (ATOMIC ? wn * WN : 0) + nf * 8 + t4 * 2;
            const float* aS = attS + hsel * 64;
            const float* aD = attD + hsel * 64;
            aSv[nf][0] = aS[idx];     aSv[nf][1] = aS[idx + 1];
            aDv[nf][0] = aD[idx];     aDv[nf][1] = aD[idx + 1];
        }
        #pragma unroll
        for (int mf = 0; mf < 2; mf++) {
            float ds0 = 0.f, dd0 = 0.f, ds1 = 0.f, dd1 = 0.f;
            #pragma unroll
            for (int nf = 0; nf < NFRAG; nf++) {
                ds0 += acc[mf][nf][0] * aSv[nf][0] + acc[mf][nf][1] * aSv[nf][1];
                dd0 += acc[mf][nf][0] * aDv[nf][0] + acc[mf][nf][1] * aDv[nf][1];
                ds1 += acc[mf][nf][2] * aSv[nf][0] + acc[mf][nf][3] * aSv[nf][1];
                dd1 += acc[mf][nf][2] * aDv[nf][0] + acc[mf][nf][3] * aDv[nf][1];
            }
            #pragma unroll
            for (int o = 1; o <= 2; o <<= 1) {
                ds0 += __shfl_xor_sync(0xffffffffu, ds0, o);
                dd0 += __shfl_xor_sync(0xffffffffu, dd0, o);
                ds1 += __shfl_xor_sync(0xffffffffu, ds1, o);
                dd1 += __shfl_xor_sync(0xffffffffu, dd1, o);
            }
            if (t4 == 0) {
                int rbase = row0 + wm * 32 + mf * 16;
                int r0r = rbase + g, r1r = rbase + g + 8;
                if (ATOMIC) {
                    if (r0r < n) { atomicAdd(&asOut[r0r], ds0); atomicAdd(&adOut[r0r], dd0); }
                    if (r1r < n) { atomicAdd(&asOut[r1r], ds1); atomicAdd(&adOut[r1r], dd1); }
                } else {
                    if (r0r < n) { asOut[r0r * 4 + hsel] = ds0; adOut[r0r * 4 + hsel] = dd0; }
                    if (r1r < n) { asOut[r1r * 4 + hsel] = ds1; adOut[r1r * 4 + hsel] = dd1; }
                }
            }
        }
    }
}

// ---------------- fused softmax + aggregation, layer 1 ----------------------
// 4 nodes per 256-thread block; 64 lanes per node; float4 per lane (256 ch).
// No smem, no syncthreads: csrc/as1 loads are lane-broadcasts within the group.
__global__ void agg1_kernel(const float* __restrict__ as1, const float* __restrict__ ad1,
                            const float* __restrict__ hm, const float* __restrict__ bias,
                            float* __restrict__ out, int n) {
    int tid = threadIdx.x;
    int sub = tid >> 6;          // node slot 0..3
    int lane = tid & 63;         // 64 lanes per node
    int node = blockIdx.x * 4 + sub;
    if (node >= n) return;
    int h = lane >> 4;           // head = (lane*4)/64
    int r0 = g_rowptr[node], r1 = g_rowptr[node + 1];
    float adv = ad1[node * 4 + h];
    float4 acc = make_float4(0.f, 0.f, 0.f, 0.f);
    float dsum = 0.f;
    #pragma unroll 2
    for (int j = r0; j < r1; j++) {
        int s = __ldg(&g_csrc[j]);
        float e = __ldg(&as1[s * 4 + h]) + adv;
        e = (e > 0.f) ? e : 0.2f * e;
        float w = __expf(e);
        float4 hv = *reinterpret_cast<const float4*>(&hm[(size_t)s * 256 + lane * 4]);
        acc.x += hv.x * w; acc.y += hv.y * w;
        acc.z += hv.z * w; acc.w += hv.w * w;
        dsum += w;
    }
    float inv = 1.f / (dsum + 1e-16f);
    float4 bv = *reinterpret_cast<const float4*>(&bias[lane * 4]);
    float o0 = acc.x * inv + bv.x;
    float o1 = acc.y * inv + bv.y;
    float o2 = acc.z * inv + bv.z;
    float o3 = acc.w * inv + bv.w;
    o0 = (o0 > 0.f) ? o0 : (__expf(o0) - 1.f);
    o1 = (o1 > 0.f) ? o1 : (__expf(o1) - 1.f);
    o2 = (o2 > 0.f) ? o2 : (__expf(o2) - 1.f);
    o3 = (o3 > 0.f) ? o3 : (__expf(o3) - 1.f);
    *reinterpret_cast<float4*>(&out[(size_t)node * 256 + lane * 4]) =
        make_float4(o0, o1, o2, o3);
}

// ---------------- fused softmax + aggregation, layer 2 ----------------------
// One warp per node; float2 per lane (64 ch). 8 nodes per 256-thread block.
__global__ void agg2_kernel(const float* __restrict__ as2, const float* __restrict__ ad2,
                            const float* __restrict__ hm, const float* __restrict__ bias,
                            float* __restrict__ out, int n) {
    int tid = threadIdx.x;
    int warp = tid >> 5, lane = tid & 31;
    int node = blockIdx.x * 8 + warp;
    if (node >= n) return;
    int r0 = g_rowptr[node], r1 = g_rowptr[node + 1];
    float adv = ad2[node];
    float2 acc = make_float2(0.f, 0.f);
    float dsum = 0.f;
    #pragma unroll 2
    for (int j = r0; j < r1; j++) {
        int s = __ldg(&g_csrc[j]);
        float e = __ldg(&as2[s]) + adv;
        e = (e > 0.f) ? e : 0.2f * e;
        float w = __expf(e);
        float2 hv = *reinterpret_cast<const float2*>(&hm[(size_t)s * 64 + lane * 2]);
        acc.x += hv.x * w; acc.y += hv.y * w;
        dsum += w;
    }
    float inv = 1.f / (dsum + 1e-16f);
    float2 bv = *reinterpret_cast<const float2*>(&bias[lane * 2]);
    *reinterpret_cast<float2*>(&out[(size_t)node * 64 + lane * 2]) =
        make_float2(acc.x * inv + bv.x, acc.y * inv + bv.y);
}

// ---------------- launch ----------------------------------------------------
extern "C" void kernel_launch(void* const* d_in, const int* in_sizes, int n_in,
                              void* d_out, int out_size) {
    const float* x   = (const float*)d_in[0];
    const int*   ei  = (const int*)d_in[1];
    const float* W1  = (const float*)d_in[2];
    const float* a1s = (const float*)d_in[3];
    const float* a1d = (const float*)d_in[4];
    const float* b1  = (const float*)d_in[5];
    const float* W2  = (const float*)d_in[6];
    const float* a2s = (const float*)d_in[7];
    const float* a2d = (const float*)d_in[8];
    const float* b2  = (const float*)d_in[9];
    float* out = (float*)d_out;

    int N = in_sizes[0] / 128;
    int E = in_sizes[1] / 2;
    int EPN = E + N;
    int NB = (N + 1023) / 1024;

    float *h1, *out1, *h2, *as1, *ad1, *as2, *ad2;
    cudaGetSymbolAddress((void**)&h1,   g_h1);
    cudaGetSymbolAddress((void**)&out1, g_out1);
    cudaGetSymbolAddress((void**)&h2,   g_h2);
    cudaGetSymbolAddress((void**)&as1,  g_as1);
    cudaGetSymbolAddress((void**)&ad1,  g_ad1);
    cudaGetSymbolAddress((void**)&as2,  g_as2);
    cudaGetSymbolAddress((void**)&ad2,  g_ad2);

    // CSR build (shared by both layers) + zero of layer2 alpha accumulators
    init_kernel<<<(N + 255) / 256, 256>>>(N);
    hist_kernel<<<(EPN + 255) / 256, 256>>>(ei, E, N);
    scan_local_kernel<<<NB, 1024>>>(N);
    scan_bsum_kernel<<<1, 64>>>(NB);
    scan_add_kernel<<<(N + 255) / 256, 256>>>(N, EPN);
    scatter_kernel<<<(EPN + 255) / 256, 256>>>(ei, E, N);

    // ---- layer 1: GEMM(+alpha) -> fused softmax+agg(+bias+ELU) ----
    gemm_tc_kernel<128, false><<<dim3(2, (N + 127) / 128), 256>>>(
        x, W1, h1, N, 128, 256, a1s, a1d, as1, ad1);
    agg1_kernel<<<(N + 3) / 4, 256>>>(as1, ad1, h1, b1, out1, N);

    // ---- layer 2: GEMM(+alpha atomic) -> fused softmax+agg(+bias) ----
    gemm_tc_kernel<64, true><<<dim3(1, (N + 127) / 128), 256>>>(
        out1, W2, h2, N, 256, 64, a2s, a2d, as2, ad2);
    agg2_kernel<<<(N + 7) / 8, 256>>>(as2, ad2, h2, b2, out, N);
}

// round 13
// speedup vs baseline: 5.9237x; 1.0484x over previous
#include <cuda_runtime.h>
#include <cuda_fp16.h>
#include <math.h>

#define MAXN 50000
#define MAXE 800000
#define MAXEPN (MAXE + MAXN)

// ---------------- scratch (device globals) ----------------------------------
__device__ __align__(16) __half g_h1[MAXN * 256];  // layer1 GEMM output (fp16) [N,4,64]
__device__ __align__(16) float g_out1[MAXN * 256]; // layer1 aggregated+elu (fp32, GEMM2 input)
__device__ __align__(16) __half g_h2[MAXN * 64];   // layer2 GEMM output (fp16)
__device__ __align__(16) float g_as1[MAXN * 4], g_ad1[MAXN * 4];
__device__ float g_as2[MAXN], g_ad2[MAXN];
__device__ int g_deg[MAXN];
__device__ int g_rowptr[MAXN + 1];
__device__ int g_cursor[MAXN];
__device__ int g_csrc[MAXEPN];                     // CSR: src per (dst-sorted) edge
__device__ int g_bsum[64];
__device__ int g_boff[64];

// ---------------- init: zero deg + layer2 alpha accumulators ----------------
__global__ void init_kernel(int n) {
    int i = blockIdx.x * blockDim.x + threadIdx.x;
    if (i < n) { g_deg[i] = 0; g_as2[i] = 0.f; g_ad2[i] = 0.f; }
}

// ---------------- CSR build --------------------------------------------------
__global__ void hist_kernel(const int* __restrict__ ei, int E, int n) {
    int idx = blockIdx.x * blockDim.x + threadIdx.x;
    if (idx >= E + n) return;
    int d = (idx < E) ? ei[E + idx] : (idx - E);
    atomicAdd(&g_deg[d], 1);
}

__global__ void scan_local_kernel(int n) {
    __shared__ int wsum[32];
    int lane = threadIdx.x & 31, wid = threadIdx.x >> 5;
    int i = blockIdx.x * 1024 + threadIdx.x;
    int v = (i < n) ? g_deg[i] : 0;
    int x = v;
    #pragma unroll
    for (int o = 1; o < 32; o <<= 1) {
        int y = __shfl_up_sync(0xffffffffu, x, o);
        if (lane >= o) x += y;
    }
    if (lane == 31) wsum[wid] = x;
    __syncthreads();
    if (wid == 0) {
        int w = wsum[lane];
        int xs = w;
        #pragma unroll
        for (int o = 1; o < 32; o <<= 1) {
            int y = __shfl_up_sync(0xffffffffu, xs, o);
            if (lane >= o) xs += y;
        }
        wsum[lane] = xs - w;
    }
    __syncthreads();
    int excl = wsum[wid] + x - v;
    if (i < n) g_rowptr[i] = excl;
    if (threadIdx.x == 1023) g_bsum[blockIdx.x] = excl + v;
}

__global__ void scan_bsum_kernel(int nb) {
    __shared__ int s[64];
    int t = threadIdx.x;
    s[t] = (t < nb) ? g_bsum[t] : 0;
    __syncthreads();
    for (int o = 1; o < 64; o <<= 1) {
        int v = (t >= o) ? s[t - o] : 0;
        __syncthreads();
        s[t] += v;
        __syncthreads();
    }
    int incl = s[t];
    g_boff[t] = incl - ((t < nb) ? g_bsum[t] : 0);
}

__global__ void scan_add_kernel(int n, int total) {
    int i = blockIdx.x * blockDim.x + threadIdx.x;
    if (i < n) {
        int r = g_rowptr[i] + g_boff[i >> 10];
        g_rowptr[i] = r;
        g_cursor[i] = r;
    }
    if (i == 0) g_rowptr[n] = total;
}

__global__ void scatter_kernel(const int* __restrict__ ei, int E, int n) {
    int idx = blockIdx.x * blockDim.x + threadIdx.x;
    if (idx >= E + n) return;
    int s, d;
    if (idx < E) { s = ei[idx]; d = ei[E + idx]; } else { s = d = idx - E; }
    int pos = atomicAdd(&g_cursor[d], 1);
    g_csrc[pos] = s;
}

// ---------------- 3xTF32 tensor-core GEMM + fused alpha epilogue ------------
__device__ __forceinline__ void split_tf32(float v, unsigned& hi, unsigned& lo) {
    unsigned h;
    asm("cvt.rna.tf32.f32 %0, %1;" : "=r"(h) : "f"(v));
    float l = v - __uint_as_float(h);
    unsigned lw;
    asm("cvt.rna.tf32.f32 %0, %1;" : "=r"(lw) : "f"(l));
    hi = h; lo = lw;
}

__device__ __forceinline__ void mma_tf32(float& c0, float& c1, float& c2, float& c3,
                                         unsigned a0, unsigned a1, unsigned a2, unsigned a3,
                                         unsigned b0, unsigned b1) {
    asm volatile(
        "mma.sync.aligned.m16n8k8.row.col.f32.tf32.tf32.f32 "
        "{%0,%1,%2,%3},{%4,%5,%6,%7},{%8,%9},{%0,%1,%2,%3};"
        : "+f"(c0), "+f"(c1), "+f"(c2), "+f"(c3)
        : "r"(a0), "r"(a1), "r"(a2), "r"(a3), "r"(b0), "r"(b1));
}

// BM=128, BN columns (128 or 64), BK=16. 256 threads = 8 warps (4 m x 2 n).
// C is written in fp16 (half2). Alpha epilogue uses exact fp32 accumulators.
template <int BN, bool ATOMIC>
__global__ void gemm_tc_kernel(const float* __restrict__ A, const float* __restrict__ B,
                               __half* __restrict__ C, int n, int k, int m,
                               const float* __restrict__ attS, const float* __restrict__ attD,
                               float* __restrict__ asOut, float* __restrict__ adOut) {
    constexpr int BM = 128, BK = 16;
    constexpr int WN = BN / 2;
    constexpr int NFRAG = WN / 8;
    constexpr int AP = BM + 8;
    constexpr int BP = BN + 8;
    constexpr int AITER = BM * BK / 4 / 256;
    constexpr int BITER = BK * BN / 4 / 256;

    __shared__ unsigned Ahi[BK][AP], Alo[BK][AP];
    __shared__ unsigned Bhi[BK][BP], Blo[BK][BP];

    int tid = threadIdx.x;
    int warp = tid >> 5, lane = tid & 31;
    int wm = warp & 3, wn = warp >> 2;
    int g = lane >> 2, t4 = lane & 3;
    int row0 = blockIdx.y * BM, col0 = blockIdx.x * BN;

    float4 aR[AITER], bR[BITER];

    auto loadTile = [&](int kt) {
        #pragma unroll
        for (int i = 0; i < AITER; i++) {
            int slot = tid + i * 256;
            int r = slot / (BK / 4), q = slot % (BK / 4);
            int gr = row0 + r;
            aR[i] = (gr < n)
                ? *reinterpret_cast<const float4*>(&A[(size_t)gr * k + kt + q * 4])
                : make_float4(0.f, 0.f, 0.f, 0.f);
        }
        #pragma unroll
        for (int i = 0; i < BITER; i++) {
            int slot = tid + i * 256;
            int kr = slot / (BN / 4), nc = slot % (BN / 4);
            bR[i] = *reinterpret_cast<const float4*>(&B[(size_t)(kt + kr) * m + col0 + nc * 4]);
        }
    };
    auto storeTile = [&]() {
        #pragma unroll
        for (int i = 0; i < AITER; i++) {
            int slot = tid + i * 256;
            int r = slot / (BK / 4), q = slot % (BK / 4);
            float v[4] = {aR[i].x, aR[i].y, aR[i].z, aR[i].w};
            #pragma unroll
            for (int j = 0; j < 4; j++) {
                unsigned h, l;
                split_tf32(v[j], h, l);
                Ahi[q * 4 + j][r] = h;
                Alo[q * 4 + j][r] = l;
            }
        }
        #pragma unroll
        for (int i = 0; i < BITER; i++) {
            int slot = tid + i * 256;
            int kr = slot / (BN / 4), nc = slot % (BN / 4);
            float v[4] = {bR[i].x, bR[i].y, bR[i].z, bR[i].w};
            #pragma unroll
            for (int j = 0; j < 4; j++) {
                unsigned h, l;
                split_tf32(v[j], h, l);
                Bhi[kr][nc * 4 + j] = h;
                Blo[kr][nc * 4 + j] = l;
            }
        }
    };

    float acc[2][NFRAG][4];
    #pragma unroll
    for (int i = 0; i < 2; i++)
        #pragma unroll
        for (int j = 0; j < NFRAG; j++)
            #pragma unroll
            for (int q = 0; q < 4; q++) acc[i][j][q] = 0.f;

    int tiles = k / BK;
    loadTile(0);
    storeTile();
    __syncthreads();

    for (int t = 0; t < tiles; t++) {
        if (t + 1 < tiles) loadTile((t + 1) * BK);
        #pragma unroll
        for (int ks = 0; ks < BK / 8; ks++) {
            int k0 = ks * 8;
            unsigned ah[2][4], al[2][4];
            #pragma unroll
            for (int mf = 0; mf < 2; mf++) {
                int rb = wm * 32 + mf * 16;
                ah[mf][0] = Ahi[k0 + t4][rb + g];
                ah[mf][1] = Ahi[k0 + t4][rb + g + 8];
                ah[mf][2] = Ahi[k0 + t4 + 4][rb + g];
                ah[mf][3] = Ahi[k0 + t4 + 4][rb + g + 8];
                al[mf][0] = Alo[k0 + t4][rb + g];
                al[mf][1] = Alo[k0 + t4][rb + g + 8];
                al[mf][2] = Alo[k0 + t4 + 4][rb + g];
                al[mf][3] = Alo[k0 + t4 + 4][rb + g + 8];
            }
            unsigned bh[NFRAG][2], bl[NFRAG][2];
            #pragma unroll
            for (int nf = 0; nf < NFRAG; nf++) {
                int cb = wn * WN + nf * 8 + g;
                bh[nf][0] = Bhi[k0 + t4][cb];
                bh[nf][1] = Bhi[k0 + t4 + 4][cb];
                bl[nf][0] = Blo[k0 + t4][cb];
                bl[nf][1] = Blo[k0 + t4 + 4][cb];
            }
            #pragma unroll
            for (int mf = 0; mf < 2; mf++)
                #pragma unroll
                for (int nf = 0; nf < NFRAG; nf++) {
                    float* c = acc[mf][nf];
                    mma_tf32(c[0], c[1], c[2], c[3],
                             ah[mf][0], ah[mf][1], ah[mf][2], ah[mf][3],
                             bh[nf][0], bh[nf][1]);
                    mma_tf32(c[0], c[1], c[2], c[3],
                             ah[mf][0], ah[mf][1], ah[mf][2], ah[mf][3],
                             bl[nf][0], bl[nf][1]);
                    mma_tf32(c[0], c[1], c[2], c[3],
                             al[mf][0], al[mf][1], al[mf][2], al[mf][3],
                             bh[nf][0], bh[nf][1]);
                }
        }
        __syncthreads();
        if (t + 1 < tiles) {
            storeTile();
            __syncthreads();
        }
    }

    // ---- write C tile (fp16) ----
    __half2* C2 = reinterpret_cast<__half2*>(C);
    #pragma unroll
    for (int mf = 0; mf < 2; mf++) {
        int rbase = row0 + wm * 32 + mf * 16;
        #pragma unroll
        for (int nf = 0; nf < NFRAG; nf++) {
            int cb = col0 + wn * WN + nf * 8 + t4 * 2;
            int r0r = rbase + g, r1r = rbase + g + 8;
            if (r0r < n)
                C2[((size_t)r0r * m + cb) >> 1] =
                    __floats2half2_rn(acc[mf][nf][0], acc[mf][nf][1]);
            if (r1r < n)
                C2[((size_t)r1r * m + cb) >> 1] =
                    __floats2half2_rn(acc[mf][nf][2], acc[mf][nf][3]);
        }
    }

    // ---- fused alpha epilogue (fp32 accumulators) ----
    {
        float aSv[NFRAG][2], aDv[NFRAG][2];
        int hsel = ATOMIC ? 0 : ((col0 + wn * WN) >> 6);
        #pragma unroll
        for (int nf = 0; nf < NFRAG; nf++) {
            int idx = (ATOMIC ? wn * WN : 0) + nf * 8 + t4 * 2;
            const float* aS = attS + hsel * 64;
            const float* aD = attD + hsel * 64;
            aSv[nf][0] = aS[idx];     aSv[nf][1] = aS[idx + 1];
            aDv[nf][0] = aD[idx];     aDv[nf][1] = aD[idx + 1];
        }
        #pragma unroll
        for (int mf = 0; mf < 2; mf++) {
            float ds0 = 0.f, dd0 = 0.f, ds1 = 0.f, dd1 = 0.f;
            #pragma unroll
            for (int nf = 0; nf < NFRAG; nf++) {
                ds0 += acc[mf][nf][0] * aSv[nf][0] + acc[mf][nf][1] * aSv[nf][1];
                dd0 += acc[mf][nf][0] * aDv[nf][0] + acc[mf][nf][1] * aDv[nf][1];
                ds1 += acc[mf][nf][2] * aSv[nf][0] + acc[mf][nf][3] * aSv[nf][1];
                dd1 += acc[mf][nf][2] * aDv[nf][0] + acc[mf][nf][3] * aDv[nf][1];
            }
            #pragma unroll
            for (int o = 1; o <= 2; o <<= 1) {
                ds0 += __shfl_xor_sync(0xffffffffu, ds0, o);
                dd0 += __shfl_xor_sync(0xffffffffu, dd0, o);
                ds1 += __shfl_xor_sync(0xffffffffu, ds1, o);
                dd1 += __shfl_xor_sync(0xffffffffu, dd1, o);
            }
            if (t4 == 0) {
                int rbase = row0 + wm * 32 + mf * 16;
                int r0r = rbase + g, r1r = rbase + g + 8;
                if (ATOMIC) {
                    if (r0r < n) { atomicAdd(&asOut[r0r], ds0); atomicAdd(&adOut[r0r], dd0); }
                    if (r1r < n) { atomicAdd(&asOut[r1r], ds1); atomicAdd(&adOut[r1r], dd1); }
                } else {
                    if (r0r < n) { asOut[r0r * 4 + hsel] = ds0; adOut[r0r * 4 + hsel] = dd0; }
                    if (r1r < n) { asOut[r1r * 4 + hsel] = ds1; adOut[r1r * 4 + hsel] = dd1; }
                }
            }
        }
    }
}

// ---------------- fused softmax + aggregation, layer 1 ----------------------
// One warp per node; 8 channels per lane via one uint4 (8 x fp16) load.
// 8 nodes per 256-thread block.
__global__ void agg1_kernel(const float* __restrict__ as1, const float* __restrict__ ad1,
                            const __half* __restrict__ hm, const float* __restrict__ bias,
                            float* __restrict__ out, int n) {
    int tid = threadIdx.x;
    int warp = tid >> 5, lane = tid & 31;
    int node = blockIdx.x * 8 + warp;
    if (node >= n) return;
    int h = lane >> 3;               // 8 lanes per head (64 ch / 8 ch-per-lane)
    int r0 = g_rowptr[node], r1 = g_rowptr[node + 1];
    float adv = ad1[node * 4 + h];
    const uint4* hm4 = reinterpret_cast<const uint4*>(hm);  // 32 uint4 per row
    float acc[8] = {};
    float dsum = 0.f;
    #pragma unroll 2
    for (int j = r0; j < r1; j++) {
        int s = __ldg(&g_csrc[j]);
        float e = __ldg(&as1[s * 4 + h]) + adv;
        e = (e > 0.f) ? e : 0.2f * e;
        float w = __expf(e);
        uint4 hv = hm4[(size_t)s * 32 + lane];
        float2 p0 = __half22float2(*reinterpret_cast<__half2*>(&hv.x));
        float2 p1 = __half22float2(*reinterpret_cast<__half2*>(&hv.y));
        float2 p2 = __half22float2(*reinterpret_cast<__half2*>(&hv.z));
        float2 p3 = __half22float2(*reinterpret_cast<__half2*>(&hv.w));
        acc[0] += p0.x * w; acc[1] += p0.y * w;
        acc[2] += p1.x * w; acc[3] += p1.y * w;
        acc[4] += p2.x * w; acc[5] += p2.y * w;
        acc[6] += p3.x * w; acc[7] += p3.y * w;
        dsum += w;
    }
    float inv = 1.f / (dsum + 1e-16f);
    size_t ob = (size_t)node * 256 + lane * 8;
    float4 b0 = *reinterpret_cast<const float4*>(&bias[lane * 8]);
    float4 b1 = *reinterpret_cast<const float4*>(&bias[lane * 8 + 4]);
    float o[8];
    o[0] = acc[0] * inv + b0.x; o[1] = acc[1] * inv + b0.y;
    o[2] = acc[2] * inv + b0.z; o[3] = acc[3] * inv + b0.w;
    o[4] = acc[4] * inv + b1.x; o[5] = acc[5] * inv + b1.y;
    o[6] = acc[6] * inv + b1.z; o[7] = acc[7] * inv + b1.w;
    #pragma unroll
    for (int i = 0; i < 8; i++) o[i] = (o[i] > 0.f) ? o[i] : (__expf(o[i]) - 1.f);
    *reinterpret_cast<float4*>(&out[ob])     = make_float4(o[0], o[1], o[2], o[3]);
    *reinterpret_cast<float4*>(&out[ob + 4]) = make_float4(o[4], o[5], o[6], o[7]);
}

// ---------------- fused softmax + aggregation, layer 2 ----------------------
// One warp per node; 2 channels per lane (half2). 8 nodes per 256-thread block.
__global__ void agg2_kernel(const float* __restrict__ as2, const float* __restrict__ ad2,
                            const __half* __restrict__ hm, const float* __restrict__ bias,
                            float* __restrict__ out, int n) {
    int tid = threadIdx.x;
    int warp = tid >> 5, lane = tid & 31;
    int node = blockIdx.x * 8 + warp;
    if (node >= n) return;
    int r0 = g_rowptr[node], r1 = g_rowptr[node + 1];
    float adv = ad2[node];
    const __half2* hm2 = reinterpret_cast<const __half2*>(hm);  // 32 half2 per row
    float2 acc = make_float2(0.f, 0.f);
    float dsum = 0.f;
    #pragma unroll 2
    for (int j = r0; j < r1; j++) {
        int s = __ldg(&g_csrc[j]);
        float e = __ldg(&as2[s]) + adv;
        e = (e > 0.f) ? e : 0.2f * e;
        float w = __expf(e);
        float2 hv = __half22float2(hm2[(size_t)s * 32 + lane]);
        acc.x += hv.x * w; acc.y += hv.y * w;
        dsum += w;
    }
    float inv = 1.f / (dsum + 1e-16f);
    float2 bv = *reinterpret_cast<const float2*>(&bias[lane * 2]);
    *reinterpret_cast<float2*>(&out[(size_t)node * 64 + lane * 2]) =
        make_float2(acc.x * inv + bv.x, acc.y * inv + bv.y);
}

// ---------------- launch ----------------------------------------------------
extern "C" void kernel_launch(void* const* d_in, const int* in_sizes, int n_in,
                              void* d_out, int out_size) {
    const float* x   = (const float*)d_in[0];
    const int*   ei  = (const int*)d_in[1];
    const float* W1  = (const float*)d_in[2];
    const float* a1s = (const float*)d_in[3];
    const float* a1d = (const float*)d_in[4];
    const float* b1  = (const float*)d_in[5];
    const float* W2  = (const float*)d_in[6];
    const float* a2s = (const float*)d_in[7];
    const float* a2d = (const float*)d_in[8];
    const float* b2  = (const float*)d_in[9];
    float* out = (float*)d_out;

    int N = in_sizes[0] / 128;
    int E = in_sizes[1] / 2;
    int EPN = E + N;
    int NB = (N + 1023) / 1024;

    float *out1, *as1, *ad1, *as2, *ad2;
    __half *h1, *h2;
    cudaGetSymbolAddress((void**)&h1,   g_h1);
    cudaGetSymbolAddress((void**)&out1, g_out1);
    cudaGetSymbolAddress((void**)&h2,   g_h2);
    cudaGetSymbolAddress((void**)&as1,  g_as1);
    cudaGetSymbolAddress((void**)&ad1,  g_ad1);
    cudaGetSymbolAddress((void**)&as2,  g_as2);
    cudaGetSymbolAddress((void**)&ad2,  g_ad2);

    // CSR build (shared by both layers) + zero of layer2 alpha accumulators
    init_kernel<<<(N + 255) / 256, 256>>>(N);
    hist_kernel<<<(EPN + 255) / 256, 256>>>(ei, E, N);
    scan_local_kernel<<<NB, 1024>>>(N);
    scan_bsum_kernel<<<1, 64>>>(NB);
    scan_add_kernel<<<(N + 255) / 256, 256>>>(N, EPN);
    scatter_kernel<<<(EPN + 255) / 256, 256>>>(ei, E, N);

    // ---- layer 1: GEMM(+alpha) -> fused softmax+agg(+bias+ELU) ----
    gemm_tc_kernel<128, false><<<dim3(2, (N + 127) / 128), 256>>>(
        x, W1, h1, N, 128, 256, a1s, a1d, as1, ad1);
    agg1_kernel<<<(N + 7) / 8, 256>>>(as1, ad1, h1, b1, out1, N);

    // ---- layer 2: GEMM(+alpha atomic) -> fused softmax+agg(+bias) ----
    gemm_tc_kernel<64, true><<<dim3(1, (N + 127) / 128), 256>>>(
        out1, W2, h2, N, 256, 64, a2s, a2d, as2, ad2);
    agg2_kernel<<<(N + 7) / 8, 256>>>(as2, ad2, h2, b2, out, N);
}

// round 14
// speedup vs baseline: 6.0153x; 1.0155x over previous
#include <cuda_runtime.h>
#include <cuda_fp16.h>
#include <math.h>

#define MAXN 50000
#define MAXE 800000
#define MAXEPN (MAXE + MAXN)

// ---------------- scratch (device globals) ----------------------------------
__device__ __align__(16) __half g_h1[MAXN * 256];  // layer1 GEMM output (fp16)
__device__ __align__(16) float g_out1[MAXN * 256]; // layer1 aggregated+elu (fp32)
__device__ __align__(16) __half g_h2[MAXN * 64];   // layer2 GEMM output (fp16)
__device__ __align__(16) float g_as1[MAXN * 4], g_ad1[MAXN * 4];
__device__ float g_as2[MAXN], g_ad2[MAXN];
__device__ int g_deg[MAXN];                        // zero at entry (BSS / self-restored)
__device__ int g_rowptr[MAXN + 1];
__device__ int g_cursor[MAXN];
__device__ int g_csrc[MAXEPN];
__device__ int g_bsum[64];

// ---------------- CSR build --------------------------------------------------
__global__ void hist_kernel(const int* __restrict__ ei, int E, int n) {
    int idx = blockIdx.x * blockDim.x + threadIdx.x;
    if (idx >= E + n) return;
    int d = (idx < E) ? __ldg(&ei[E + idx]) : (idx - E);
    atomicAdd(&g_deg[d], 1);
}

// per-1024 exclusive scan + block total; also re-zeroes g_deg for next replay
__global__ void scan_local_kernel(int n) {
    __shared__ int wsum[32];
    int lane = threadIdx.x & 31, wid = threadIdx.x >> 5;
    int i = blockIdx.x * 1024 + threadIdx.x;
    int v = (i < n) ? g_deg[i] : 0;
    if (i < n) g_deg[i] = 0;          // self-restore invariant
    int x = v;
    #pragma unroll
    for (int o = 1; o < 32; o <<= 1) {
        int y = __shfl_up_sync(0xffffffffu, x, o);
        if (lane >= o) x += y;
    }
    if (lane == 31) wsum[wid] = x;
    __syncthreads();
    if (wid == 0) {
        int w = wsum[lane];
        int xs = w;
        #pragma unroll
        for (int o = 1; o < 32; o <<= 1) {
            int y = __shfl_up_sync(0xffffffffu, xs, o);
            if (lane >= o) xs += y;
        }
        wsum[lane] = xs - w;
    }
    __syncthreads();
    int excl = wsum[wid] + x - v;
    if (i < n) g_rowptr[i] = excl;
    if (threadIdx.x == 1023) g_bsum[blockIdx.x] = excl + v;
}

// fused: redundant per-block scan of <=64 block sums + offset add + cursor init
__global__ void scan_add_kernel(int n, int total, int nb) {
    __shared__ int s[64];
    if (threadIdx.x < 64) s[threadIdx.x] = (threadIdx.x < (unsigned)nb) ? g_bsum[threadIdx.x] : 0;
    __syncthreads();
    for (int o = 1; o < 64; o <<= 1) {
        int v = 0;
        if (threadIdx.x < 64 && threadIdx.x >= (unsigned)o) v = s[threadIdx.x - o];
        __syncthreads();
        if (threadIdx.x < 64) s[threadIdx.x] += v;
        __syncthreads();
    }
    int i = blockIdx.x * blockDim.x + threadIdx.x;
    if (i < n) {
        int blk = i >> 10;
        int boff = (blk > 0) ? s[blk - 1] : 0;
        int r = g_rowptr[i] + boff;
        g_rowptr[i] = r;
        g_cursor[i] = r;
    }
    if (i == 0) g_rowptr[n] = total;
}

__global__ void scatter_kernel(const int* __restrict__ ei, int E, int n) {
    int idx = blockIdx.x * blockDim.x + threadIdx.x;
    if (idx >= E + n) return;
    int s, d;
    if (idx < E) { s = __ldg(&ei[idx]); d = __ldg(&ei[E + idx]); } else { s = d = idx - E; }
    int pos = atomicAdd(&g_cursor[d], 1);
    g_csrc[pos] = s;
}

// ---------------- 3xTF32 tensor-core GEMM + fused alpha epilogue ------------
__device__ __forceinline__ void split_tf32(float v, unsigned& hi, unsigned& lo) {
    unsigned h;
    asm("cvt.rna.tf32.f32 %0, %1;" : "=r"(h) : "f"(v));
    float l = v - __uint_as_float(h);
    unsigned lw;
    asm("cvt.rna.tf32.f32 %0, %1;" : "=r"(lw) : "f"(l));
    hi = h; lo = lw;
}

__device__ __forceinline__ void mma_tf32(float& c0, float& c1, float& c2, float& c3,
                                         unsigned a0, unsigned a1, unsigned a2, unsigned a3,
                                         unsigned b0, unsigned b1) {
    asm volatile(
        "mma.sync.aligned.m16n8k8.row.col.f32.tf32.tf32.f32 "
        "{%0,%1,%2,%3},{%4,%5,%6,%7},{%8,%9},{%0,%1,%2,%3};"
        : "+f"(c0), "+f"(c1), "+f"(c2), "+f"(c3)
        : "r"(a0), "r"(a1), "r"(a2), "r"(a3), "r"(b0), "r"(b1));
}

// BM=128, BN in {128, 64}, BK=16. 256 threads = 8 warps (4 m x 2 n).
// C written fp16. Alpha epilogue from exact fp32 accumulators.
// REDUCE=false (BN=128): warp's 64-col span == one head -> direct store.
// REDUCE=true  (BN=64): two wn-warps combine halves via smem -> direct store.
template <int BN, bool REDUCE>
__global__ void gemm_tc_kernel(const float* __restrict__ A, const float* __restrict__ B,
                               __half* __restrict__ C, int n, int k, int m,
                               const float* __restrict__ attS, const float* __restrict__ attD,
                               float* __restrict__ asOut, float* __restrict__ adOut) {
    constexpr int BM = 128, BK = 16;
    constexpr int WN = BN / 2;
    constexpr int NFRAG = WN / 8;
    constexpr int AP = BM + 8;
    constexpr int BP = BN + 8;
    constexpr int AITER = BM * BK / 4 / 256;
    constexpr int BITER = BK * BN / 4 / 256;

    __shared__ unsigned Ahi[BK][AP], Alo[BK][AP];
    __shared__ unsigned Bhi[BK][BP], Blo[BK][BP];

    int tid = threadIdx.x;
    int warp = tid >> 5, lane = tid & 31;
    int wm = warp & 3, wn = warp >> 2;
    int g = lane >> 2, t4 = lane & 3;
    int row0 = blockIdx.y * BM, col0 = blockIdx.x * BN;

    float4 aR[AITER], bR[BITER];

    auto loadTile = [&](int kt) {
        #pragma unroll
        for (int i = 0; i < AITER; i++) {
            int slot = tid + i * 256;
            int r = slot / (BK / 4), q = slot % (BK / 4);
            int gr = row0 + r;
            aR[i] = (gr < n)
                ? *reinterpret_cast<const float4*>(&A[(size_t)gr * k + kt + q * 4])
                : make_float4(0.f, 0.f, 0.f, 0.f);
        }
        #pragma unroll
        for (int i = 0; i < BITER; i++) {
            int slot = tid + i * 256;
            int kr = slot / (BN / 4), nc = slot % (BN / 4);
            bR[i] = *reinterpret_cast<const float4*>(&B[(size_t)(kt + kr) * m + col0 + nc * 4]);
        }
    };
    auto storeTile = [&]() {
        #pragma unroll
        for (int i = 0; i < AITER; i++) {
            int slot = tid + i * 256;
            int r = slot / (BK / 4), q = slot % (BK / 4);
            float v[4] = {aR[i].x, aR[i].y, aR[i].z, aR[i].w};
            #pragma unroll
            for (int j = 0; j < 4; j++) {
                unsigned h, l;
                split_tf32(v[j], h, l);
                Ahi[q * 4 + j][r] = h;
                Alo[q * 4 + j][r] = l;
            }
        }
        #pragma unroll
        for (int i = 0; i < BITER; i++) {
            int slot = tid + i * 256;
            int kr = slot / (BN / 4), nc = slot % (BN / 4);
            float v[4] = {bR[i].x, bR[i].y, bR[i].z, bR[i].w};
            #pragma unroll
            for (int j = 0; j < 4; j++) {
                unsigned h, l;
                split_tf32(v[j], h, l);
                Bhi[kr][nc * 4 + j] = h;
                Blo[kr][nc * 4 + j] = l;
            }
        }
    };

    float acc[2][NFRAG][4];
    #pragma unroll
    for (int i = 0; i < 2; i++)
        #pragma unroll
        for (int j = 0; j < NFRAG; j++)
            #pragma unroll
            for (int q = 0; q < 4; q++) acc[i][j][q] = 0.f;

    int tiles = k / BK;
    loadTile(0);
    storeTile();
    __syncthreads();

    for (int t = 0; t < tiles; t++) {
        if (t + 1 < tiles) loadTile((t + 1) * BK);
        #pragma unroll
        for (int ks = 0; ks < BK / 8; ks++) {
            int k0 = ks * 8;
            unsigned ah[2][4], al[2][4];
            #pragma unroll
            for (int mf = 0; mf < 2; mf++) {
                int rb = wm * 32 + mf * 16;
                ah[mf][0] = Ahi[k0 + t4][rb + g];
                ah[mf][1] = Ahi[k0 + t4][rb + g + 8];
                ah[mf][2] = Ahi[k0 + t4 + 4][rb + g];
                ah[mf][3] = Ahi[k0 + t4 + 4][rb + g + 8];
                al[mf][0] = Alo[k0 + t4][rb + g];
                al[mf][1] = Alo[k0 + t4][rb + g + 8];
                al[mf][2] = Alo[k0 + t4 + 4][rb + g];
                al[mf][3] = Alo[k0 + t4 + 4][rb + g + 8];
            }
            unsigned bh[NFRAG][2], bl[NFRAG][2];
            #pragma unroll
            for (int nf = 0; nf < NFRAG; nf++) {
                int cb = wn * WN + nf * 8 + g;
                bh[nf][0] = Bhi[k0 + t4][cb];
                bh[nf][1] = Bhi[k0 + t4 + 4][cb];
                bl[nf][0] = Blo[k0 + t4][cb];
                bl[nf][1] = Blo[k0 + t4 + 4][cb];
            }
            #pragma unroll
            for (int mf = 0; mf < 2; mf++)
                #pragma unroll
                for (int nf = 0; nf < NFRAG; nf++) {
                    float* c = acc[mf][nf];
                    mma_tf32(c[0], c[1], c[2], c[3],
                             ah[mf][0], ah[mf][1], ah[mf][2], ah[mf][3],
                             bh[nf][0], bh[nf][1]);
                    mma_tf32(c[0], c[1], c[2], c[3],
                             ah[mf][0], ah[mf][1], ah[mf][2], ah[mf][3],
                             bl[nf][0], bl[nf][1]);
                    mma_tf32(c[0], c[1], c[2], c[3],
                             al[mf][0], al[mf][1], al[mf][2], al[mf][3],
                             bh[nf][0], bh[nf][1]);
                }
        }
        __syncthreads();
        if (t + 1 < tiles) {
            storeTile();
            __syncthreads();
        }
    }

    // ---- write C tile (fp16) ----
    __half2* C2 = reinterpret_cast<__half2*>(C);
    #pragma unroll
    for (int mf = 0; mf < 2; mf++) {
        int rbase = row0 + wm * 32 + mf * 16;
        #pragma unroll
        for (int nf = 0; nf < NFRAG; nf++) {
            int cb = col0 + wn * WN + nf * 8 + t4 * 2;
            int r0r = rbase + g, r1r = rbase + g + 8;
            if (r0r < n)
                C2[((size_t)r0r * m + cb) >> 1] =
                    __floats2half2_rn(acc[mf][nf][0], acc[mf][nf][1]);
            if (r1r < n)
                C2[((size_t)r1r * m + cb) >> 1] =
                    __floats2half2_rn(acc[mf][nf][2], acc[mf][nf][3]);
        }
    }

    // ---- fused alpha epilogue ----
    {
        float aSv[NFRAG][2], aDv[NFRAG][2];
        int hsel = REDUCE ? 0 : ((col0 + wn * WN) >> 6);
        #pragma unroll
        for (int nf = 0; nf < NFRAG; nf++) {
            int idx = (REDUCE ? wn * WN : 0) + nf * 8 + t4 * 2;
            const float* aS = attS + hsel * 64;
            const float* aD = attD + hsel * 64;
            aSv[nf][0] = aS[idx];     aSv[nf][1] = aS[idx + 1];
            aDv[nf][0] = aD[idx];     aDv[nf][1] = aD[idx + 1];
        }
        if constexpr (REDUCE) {
            __shared__ float sDS[2][BM], sDD[2][BM];
            #pragma unroll
            for (int mf = 0; mf < 2; mf++) {
                float ds0 = 0.f, dd0 = 0.f, ds1 = 0.f, dd1 = 0.f;
                #pragma unroll
                for (int nf = 0; nf < NFRAG; nf++) {
                    ds0 += acc[mf][nf][0] * aSv[nf][0] + acc[mf][nf][1] * aSv[nf][1];
                    dd0 += acc[mf][nf][0] * aDv[nf][0] + acc[mf][nf][1] * aDv[nf][1];
                    ds1 += acc[mf][nf][2] * aSv[nf][0] + acc[mf][nf][3] * aSv[nf][1];
                    dd1 += acc[mf][nf][2] * aDv[nf][0] + acc[mf][nf][3] * aDv[nf][1];
                }
                #pragma unroll
                for (int o = 1; o <= 2; o <<= 1) {
                    ds0 += __shfl_xor_sync(0xffffffffu, ds0, o);
                    dd0 += __shfl_xor_sync(0xffffffffu, dd0, o);
                    ds1 += __shfl_xor_sync(0xffffffffu, ds1, o);
                    dd1 += __shfl_xor_sync(0xffffffffu, dd1, o);
                }
                if (t4 == 0) {
                    int rl = wm * 32 + mf * 16 + g;
                    sDS[wn][rl] = ds0;     sDD[wn][rl] = dd0;
                    sDS[wn][rl + 8] = ds1; sDD[wn][rl + 8] = dd1;
                }
            }
            __syncthreads();
            if (tid < BM) {
                int gr = row0 + tid;
                if (gr < n) {
                    asOut[gr] = sDS[0][tid] + sDS[1][tid];
                    adOut[gr] = sDD[0][tid] + sDD[1][tid];
                }
            }
        } else {
            #pragma unroll
            for (int mf = 0; mf < 2; mf++) {
                float ds0 = 0.f, dd0 = 0.f, ds1 = 0.f, dd1 = 0.f;
                #pragma unroll
                for (int nf = 0; nf < NFRAG; nf++) {
                    ds0 += acc[mf][nf][0] * aSv[nf][0] + acc[mf][nf][1] * aSv[nf][1];
                    dd0 += acc[mf][nf][0] * aDv[nf][0] + acc[mf][nf][1] * aDv[nf][1];
                    ds1 += acc[mf][nf][2] * aSv[nf][0] + acc[mf][nf][3] * aSv[nf][1];
                    dd1 += acc[mf][nf][2] * aDv[nf][0] + acc[mf][nf][3] * aDv[nf][1];
                }
                #pragma unroll
                for (int o = 1; o <= 2; o <<= 1) {
                    ds0 += __shfl_xor_sync(0xffffffffu, ds0, o);
                    dd0 += __shfl_xor_sync(0xffffffffu, dd0, o);
                    ds1 += __shfl_xor_sync(0xffffffffu, ds1, o);
                    dd1 += __shfl_xor_sync(0xffffffffu, dd1, o);
                }
                if (t4 == 0) {
                    int rbase = row0 + wm * 32 + mf * 16;
                    int r0r = rbase + g, r1r = rbase + g + 8;
                    if (r0r < n) { asOut[r0r * 4 + hsel] = ds0; adOut[r0r * 4 + hsel] = dd0; }
                    if (r1r < n) { asOut[r1r * 4 + hsel] = ds1; adOut[r1r * 4 + hsel] = dd1; }
                }
            }
        }
    }
}

// ---------------- fused softmax + aggregation, layer 1 ----------------------
// One warp per node; 8 fp16 channels per lane via uint4; batched-4 edge loop.
__global__ void agg1_kernel(const float* __restrict__ as1, const float* __restrict__ ad1,
                            const __half* __restrict__ hm, const float* __restrict__ bias,
                            float* __restrict__ out, int n) {
    int tid = threadIdx.x;
    int warp = tid >> 5, lane = tid & 31;
    int node = blockIdx.x * 8 + warp;
    if (node >= n) return;
    int h = lane >> 3;
    int r0 = g_rowptr[node], r1 = g_rowptr[node + 1];
    float adv = ad1[node * 4 + h];
    const uint4* hm4 = reinterpret_cast<const uint4*>(hm);
    float acc[8] = {};
    float dsum = 0.f;
    int j = r0;
    for (; j + 4 <= r1; j += 4) {
        int s0 = __ldg(&g_csrc[j]);
        int s1 = __ldg(&g_csrc[j + 1]);
        int s2 = __ldg(&g_csrc[j + 2]);
        int s3 = __ldg(&g_csrc[j + 3]);
        float e0 = __ldg(&as1[s0 * 4 + h]);
        float e1 = __ldg(&as1[s1 * 4 + h]);
        float e2 = __ldg(&as1[s2 * 4 + h]);
        float e3 = __ldg(&as1[s3 * 4 + h]);
        uint4 v0 = hm4[(size_t)s0 * 32 + lane];
        uint4 v1 = hm4[(size_t)s1 * 32 + lane];
        uint4 v2 = hm4[(size_t)s2 * 32 + lane];
        uint4 v3 = hm4[(size_t)s3 * 32 + lane];
        e0 += adv; e0 = (e0 > 0.f) ? e0 : 0.2f * e0; float w0 = __expf(e0);
        e1 += adv; e1 = (e1 > 0.f) ? e1 : 0.2f * e1; float w1 = __expf(e1);
        e2 += adv; e2 = (e2 > 0.f) ? e2 : 0.2f * e2; float w2 = __expf(e2);
        e3 += adv; e3 = (e3 > 0.f) ? e3 : 0.2f * e3; float w3 = __expf(e3);
        dsum += w0 + w1 + w2 + w3;
        {
            float2 p;
            p = __half22float2(*reinterpret_cast<__half2*>(&v0.x)); acc[0] += p.x * w0; acc[1] += p.y * w0;
            p = __half22float2(*reinterpret_cast<__half2*>(&v0.y)); acc[2] += p.x * w0; acc[3] += p.y * w0;
            p = __half22float2(*reinterpret_cast<__half2*>(&v0.z)); acc[4] += p.x * w0; acc[5] += p.y * w0;
            p = __half22float2(*reinterpret_cast<__half2*>(&v0.w)); acc[6] += p.x * w0; acc[7] += p.y * w0;
            p = __half22float2(*reinterpret_cast<__half2*>(&v1.x)); acc[0] += p.x * w1; acc[1] += p.y * w1;
            p = __half22float2(*reinterpret_cast<__half2*>(&v1.y)); acc[2] += p.x * w1; acc[3] += p.y * w1;
            p = __half22float2(*reinterpret_cast<__half2*>(&v1.z)); acc[4] += p.x * w1; acc[5] += p.y * w1;
            p = __half22float2(*reinterpret_cast<__half2*>(&v1.w)); acc[6] += p.x * w1; acc[7] += p.y * w1;
            p = __half22float2(*reinterpret_cast<__half2*>(&v2.x)); acc[0] += p.x * w2; acc[1] += p.y * w2;
            p = __half22float2(*reinterpret_cast<__half2*>(&v2.y)); acc[2] += p.x * w2; acc[3] += p.y * w2;
            p = __half22float2(*reinterpret_cast<__half2*>(&v2.z)); acc[4] += p.x * w2; acc[5] += p.y * w2;
            p = __half22float2(*reinterpret_cast<__half2*>(&v2.w)); acc[6] += p.x * w2; acc[7] += p.y * w2;
            p = __half22float2(*reinterpret_cast<__half2*>(&v3.x)); acc[0] += p.x * w3; acc[1] += p.y * w3;
            p = __half22float2(*reinterpret_cast<__half2*>(&v3.y)); acc[2] += p.x * w3; acc[3] += p.y * w3;
            p = __half22float2(*reinterpret_cast<__half2*>(&v3.z)); acc[4] += p.x * w3; acc[5] += p.y * w3;
            p = __half22float2(*reinterpret_cast<__half2*>(&v3.w)); acc[6] += p.x * w3; acc[7] += p.y * w3;
        }
    }
    for (; j < r1; j++) {
        int s = __ldg(&g_csrc[j]);
        float e = __ldg(&as1[s * 4 + h]) + adv;
        e = (e > 0.f) ? e : 0.2f * e;
        float w = __expf(e);
        uint4 hv = hm4[(size_t)s * 32 + lane];
        float2 p;
        p = __half22float2(*reinterpret_cast<__half2*>(&hv.x)); acc[0] += p.x * w; acc[1] += p.y * w;
        p = __half22float2(*reinterpret_cast<__half2*>(&hv.y)); acc[2] += p.x * w; acc[3] += p.y * w;
        p = __half22float2(*reinterpret_cast<__half2*>(&hv.z)); acc[4] += p.x * w; acc[5] += p.y * w;
        p = __half22float2(*reinterpret_cast<__half2*>(&hv.w)); acc[6] += p.x * w; acc[7] += p.y * w;
        dsum += w;
    }
    float inv = 1.f / (dsum + 1e-16f);
    size_t ob = (size_t)node * 256 + lane * 8;
    float4 b0 = *reinterpret_cast<const float4*>(&bias[lane * 8]);
    float4 b1 = *reinterpret_cast<const float4*>(&bias[lane * 8 + 4]);
    float o[8];
    o[0] = acc[0] * inv + b0.x; o[1] = acc[1] * inv + b0.y;
    o[2] = acc[2] * inv + b0.z; o[3] = acc[3] * inv + b0.w;
    o[4] = acc[4] * inv + b1.x; o[5] = acc[5] * inv + b1.y;
    o[6] = acc[6] * inv + b1.z; o[7] = acc[7] * inv + b1.w;
    #pragma unroll
    for (int i = 0; i < 8; i++) o[i] = (o[i] > 0.f) ? o[i] : (__expf(o[i]) - 1.f);
    *reinterpret_cast<float4*>(&out[ob])     = make_float4(o[0], o[1], o[2], o[3]);
    *reinterpret_cast<float4*>(&out[ob + 4]) = make_float4(o[4], o[5], o[6], o[7]);
}

// ---------------- fused softmax + aggregation, layer 2 ----------------------
// One warp per node; half2 per lane; batched-4 edge loop.
__global__ void agg2_kernel(const float* __restrict__ as2, const float* __restrict__ ad2,
                            const __half* __restrict__ hm, const float* __restrict__ bias,
                            float* __restrict__ out, int n) {
    int tid = threadIdx.x;
    int warp = tid >> 5, lane = tid & 31;
    int node = blockIdx.x * 8 + warp;
    if (node >= n) return;
    int r0 = g_rowptr[node], r1 = g_rowptr[node + 1];
    float adv = ad2[node];
    const __half2* hm2 = reinterpret_cast<const __half2*>(hm);
    float2 acc = make_float2(0.f, 0.f);
    float dsum = 0.f;
    int j = r0;
    for (; j + 4 <= r1; j += 4) {
        int s0 = __ldg(&g_csrc[j]);
        int s1 = __ldg(&g_csrc[j + 1]);
        int s2 = __ldg(&g_csrc[j + 2]);
        int s3 = __ldg(&g_csrc[j + 3]);
        float e0 = __ldg(&as2[s0]);
        float e1 = __ldg(&as2[s1]);
        float e2 = __ldg(&as2[s2]);
        float e3 = __ldg(&as2[s3]);
        float2 v0 = __half22float2(hm2[(size_t)s0 * 32 + lane]);
        float2 v1 = __half22float2(hm2[(size_t)s1 * 32 + lane]);
        float2 v2 = __half22float2(hm2[(size_t)s2 * 32 + lane]);
        float2 v3 = __half22float2(hm2[(size_t)s3 * 32 + lane]);
        e0 += adv; e0 = (e0 > 0.f) ? e0 : 0.2f * e0; float w0 = __expf(e0);
        e1 += adv; e1 = (e1 > 0.f) ? e1 : 0.2f * e1; float w1 = __expf(e1);
        e2 += adv; e2 = (e2 > 0.f) ? e2 : 0.2f * e2; float w2 = __expf(e2);
        e3 += adv; e3 = (e3 > 0.f) ? e3 : 0.2f * e3; float w3 = __expf(e3);
        acc.x += v0.x * w0 + v1.x * w1 + v2.x * w2 + v3.x * w3;
        acc.y += v0.y * w0 + v1.y * w1 + v2.y * w2 + v3.y * w3;
        dsum += w0 + w1 + w2 + w3;
    }
    for (; j < r1; j++) {
        int s = __ldg(&g_csrc[j]);
        float e = __ldg(&as2[s]) + adv;
        e = (e > 0.f) ? e : 0.2f * e;
        float w = __expf(e);
        float2 hv = __half22float2(hm2[(size_t)s * 32 + lane]);
        acc.x += hv.x * w; acc.y += hv.y * w;
        dsum += w;
    }
    float inv = 1.f / (dsum + 1e-16f);
    float2 bv = *reinterpret_cast<const float2*>(&bias[lane * 2]);
    *reinterpret_cast<float2*>(&out[(size_t)node * 64 + lane * 2]) =
        make_float2(acc.x * inv + bv.x, acc.y * inv + bv.y);
}

// ---------------- launch ----------------------------------------------------
extern "C" void kernel_launch(void* const* d_in, const int* in_sizes, int n_in,
                              void* d_out, int out_size) {
    const float* x   = (const float*)d_in[0];
    const int*   ei  = (const int*)d_in[1];
    const float* W1  = (const float*)d_in[2];
    const float* a1s = (const float*)d_in[3];
    const float* a1d = (const float*)d_in[4];
    const float* b1  = (const float*)d_in[5];
    const float* W2  = (const float*)d_in[6];
    const float* a2s = (const float*)d_in[7];
    const float* a2d = (const float*)d_in[8];
    const float* b2  = (const float*)d_in[9];
    float* out = (float*)d_out;

    int N = in_sizes[0] / 128;
    int E = in_sizes[1] / 2;
    int EPN = E + N;
    int NB = (N + 1023) / 1024;

    float *out1, *as1, *ad1, *as2, *ad2;
    __half *h1, *h2;
    cudaGetSymbolAddress((void**)&h1,   g_h1);
    cudaGetSymbolAddress((void**)&out1, g_out1);
    cudaGetSymbolAddress((void**)&h2,   g_h2);
    cudaGetSymbolAddress((void**)&as1,  g_as1);
    cudaGetSymbolAddress((void**)&ad1,  g_ad1);
    cudaGetSymbolAddress((void**)&as2,  g_as2);
    cudaGetSymbolAddress((void**)&ad2,  g_ad2);

    // CSR build (g_deg is zero on entry: BSS-init on first call, self-restored after)
    hist_kernel<<<(EPN + 255) / 256, 256>>>(ei, E, N);
    scan_local_kernel<<<NB, 1024>>>(N);
    scan_add_kernel<<<(N + 255) / 256, 256>>>(N, EPN, NB);
    scatter_kernel<<<(EPN + 255) / 256, 256>>>(ei, E, N);

    // ---- layer 1: GEMM(+alpha) -> fused softmax+agg(+bias+ELU) ----
    gemm_tc_kernel<128, false><<<dim3(2, (N + 127) / 128), 256>>>(
        x, W1, h1, N, 128, 256, a1s, a1d, as1, ad1);
    agg1_kernel<<<(N + 7) / 8, 256>>>(as1, ad1, h1, b1, out1, N);

    // ---- layer 2: GEMM(+alpha smem-reduce) -> fused softmax+agg(+bias) ----
    gemm_tc_kernel<64, true><<<dim3(1, (N + 127) / 128), 256>>>(
        out1, W2, h2, N, 256, 64, a2s, a2d, as2, ad2);
    agg2_kernel<<<(N + 7) / 8, 256>>>(as2, ad2, h2, b2, out, N);
}

// round 16
// speedup vs baseline: 6.3577x; 1.0569x over previous
#include <cuda_runtime.h>
#include <cuda_fp16.h>
#include <math.h>

#define MAXN 50000
#define MAXE 800000
#define MAXEPN (MAXE + MAXN)

// ---------------- scratch (device globals) ----------------------------------
__device__ __align__(16) __half g_h1[MAXN * 256];  // layer1 GEMM output (fp16)
__device__ __align__(16) float g_out1[MAXN * 256]; // layer1 aggregated+elu (fp32)
__device__ __align__(16) __half g_h2[MAXN * 64];   // layer2 GEMM output (fp16)
__device__ __align__(16) float g_as1[MAXN * 4], g_ad1[MAXN * 4];
__device__ float g_as2[MAXN], g_ad2[MAXN];
__device__ int g_deg[MAXN];                        // zero at entry (BSS / self-restored)
__device__ int g_rowptr[MAXN + 1];
__device__ int g_cursor[MAXN];
__device__ int g_csrc[MAXEPN];
__device__ int g_bsum[64];

// ---------------- stream/event resources (created once, pre-checkpoint) -----
static struct GpuRes {
    cudaStream_t s2;
    cudaEvent_t evFork, evJoin;
    GpuRes() {
        cudaStreamCreateWithFlags(&s2, cudaStreamNonBlocking);
        cudaEventCreateWithFlags(&evFork, cudaEventDisableTiming);
        cudaEventCreateWithFlags(&evJoin, cudaEventDisableTiming);
    }
} g_res;

// ---------------- CSR build --------------------------------------------------
// 4 edges per thread (int4 loads) for MLP on the atomic path.
__global__ void hist_kernel(const int* __restrict__ ei, int E, int n) {
    int idx = blockIdx.x * blockDim.x + threadIdx.x;
    int EQ = E >> 2;
    if (idx < EQ) {
        int4 d4 = *reinterpret_cast<const int4*>(&ei[E + idx * 4]);
        atomicAdd(&g_deg[d4.x], 1);
        atomicAdd(&g_deg[d4.y], 1);
        atomicAdd(&g_deg[d4.z], 1);
        atomicAdd(&g_deg[d4.w], 1);
    } else if (idx < EQ + n) {
        atomicAdd(&g_deg[idx - EQ], 1);   // self-loop
    }
}

// per-1024 exclusive scan + block total; also re-zeroes g_deg for next replay
__global__ void scan_local_kernel(int n) {
    __shared__ int wsum[32];
    int lane = threadIdx.x & 31, wid = threadIdx.x >> 5;
    int i = blockIdx.x * 1024 + threadIdx.x;
    int v = (i < n) ? g_deg[i] : 0;
    if (i < n) g_deg[i] = 0;          // self-restore invariant
    int x = v;
    #pragma unroll
    for (int o = 1; o < 32; o <<= 1) {
        int y = __shfl_up_sync(0xffffffffu, x, o);
        if (lane >= o) x += y;
    }
    if (lane == 31) wsum[wid] = x;
    __syncthreads();
    if (wid == 0) {
        int w = wsum[lane];
        int xs = w;
        #pragma unroll
        for (int o = 1; o < 32; o <<= 1) {
            int y = __shfl_up_sync(0xffffffffu, xs, o);
            if (lane >= o) xs += y;
        }
        wsum[lane] = xs - w;
    }
    __syncthreads();
    int excl = wsum[wid] + x - v;
    if (i < n) g_rowptr[i] = excl;
    if (threadIdx.x == 1023) g_bsum[blockIdx.x] = excl + v;
}

// fused: redundant per-block scan of <=64 block sums + offset add + cursor init
__global__ void scan_add_kernel(int n, int total, int nb) {
    __shared__ int s[64];
    if (threadIdx.x < 64) s[threadIdx.x] = (threadIdx.x < (unsigned)nb) ? g_bsum[threadIdx.x] : 0;
    __syncthreads();
    for (int o = 1; o < 64; o <<= 1) {
        int v = 0;
        if (threadIdx.x < 64 && threadIdx.x >= (unsigned)o) v = s[threadIdx.x - o];
        __syncthreads();
        if (threadIdx.x < 64) s[threadIdx.x] += v;
        __syncthreads();
    }
    int i = blockIdx.x * blockDim.x + threadIdx.x;
    if (i < n) {
        int blk = i >> 10;
        int boff = (blk > 0) ? s[blk - 1] : 0;
        int r = g_rowptr[i] + boff;
        g_rowptr[i] = r;
        g_cursor[i] = r;
    }
    if (i == 0) g_rowptr[n] = total;
}

// 4 edges per thread for MLP on the atomic-return path.
__global__ void scatter_kernel(const int* __restrict__ ei, int E, int n) {
    int idx = blockIdx.x * blockDim.x + threadIdx.x;
    int EQ = E >> 2;
    if (idx < EQ) {
        int4 s4 = *reinterpret_cast<const int4*>(&ei[idx * 4]);
        int4 d4 = *reinterpret_cast<const int4*>(&ei[E + idx * 4]);
        int p0 = atomicAdd(&g_cursor[d4.x], 1);
        int p1 = atomicAdd(&g_cursor[d4.y], 1);
        int p2 = atomicAdd(&g_cursor[d4.z], 1);
        int p3 = atomicAdd(&g_cursor[d4.w], 1);
        g_csrc[p0] = s4.x;
        g_csrc[p1] = s4.y;
        g_csrc[p2] = s4.z;
        g_csrc[p3] = s4.w;
    } else if (idx < EQ + n) {
        int node = idx - EQ;
        int pos = atomicAdd(&g_cursor[node], 1);
        g_csrc[pos] = node;
    }
}

// ---------------- 3xTF32 tensor-core GEMM + fused alpha epilogue ------------
__device__ __forceinline__ void split_tf32(float v, unsigned& hi, unsigned& lo) {
    unsigned h;
    asm("cvt.rna.tf32.f32 %0, %1;" : "=r"(h) : "f"(v));
    float l = v - __uint_as_float(h);
    unsigned lw;
    asm("cvt.rna.tf32.f32 %0, %1;" : "=r"(lw) : "f"(l));
    hi = h; lo = lw;
}

__device__ __forceinline__ void mma_tf32(float& c0, float& c1, float& c2, float& c3,
                                         unsigned a0, unsigned a1, unsigned a2, unsigned a3,
                                         unsigned b0, unsigned b1) {
    asm volatile(
        "mma.sync.aligned.m16n8k8.row.col.f32.tf32.tf32.f32 "
        "{%0,%1,%2,%3},{%4,%5,%6,%7},{%8,%9},{%0,%1,%2,%3};"
        : "+f"(c0), "+f"(c1), "+f"(c2), "+f"(c3)
        : "r"(a0), "r"(a1), "r"(a2), "r"(a3), "r"(b0), "r"(b1));
}

// BM=128, BN in {128, 64}, BK=16. 256 threads = 8 warps (4 m x 2 n).
template <int BN, bool REDUCE>
__global__ void gemm_tc_kernel(const float* __restrict__ A, const float* __restrict__ B,
                               __half* __restrict__ C, int n, int k, int m,
                               const float* __restrict__ attS, const float* __restrict__ attD,
                               float* __restrict__ asOut, float* __restrict__ adOut) {
    constexpr int BM = 128, BK = 16;
    constexpr int WN = BN / 2;
    constexpr int NFRAG = WN / 8;
    constexpr int AP = BM + 8;
    constexpr int BP = BN + 8;
    constexpr int AITER = BM * BK / 4 / 256;
    constexpr int BITER = BK * BN / 4 / 256;

    __shared__ unsigned Ahi[BK][AP], Alo[BK][AP];
    __shared__ unsigned Bhi[BK][BP], Blo[BK][BP];

    int tid = threadIdx.x;
    int warp = tid >> 5, lane = tid & 31;
    int wm = warp & 3, wn = warp >> 2;
    int g = lane >> 2, t4 = lane & 3;
    int row0 = blockIdx.y * BM, col0 = blockIdx.x * BN;

    float4 aR[AITER], bR[BITER];

    auto loadTile = [&](int kt) {
        #pragma unroll
        for (int i = 0; i < AITER; i++) {
            int slot = tid + i * 256;
            int r = slot / (BK / 4), q = slot % (BK / 4);
            int gr = row0 + r;
            aR[i] = (gr < n)
                ? *reinterpret_cast<const float4*>(&A[(size_t)gr * k + kt + q * 4])
                : make_float4(0.f, 0.f, 0.f, 0.f);
        }
        #pragma unroll
        for (int i = 0; i < BITER; i++) {
            int slot = tid + i * 256;
            int kr = slot / (BN / 4), nc = slot % (BN / 4);
            bR[i] = *reinterpret_cast<const float4*>(&B[(size_t)(kt + kr) * m + col0 + nc * 4]);
        }
    };
    auto storeTile = [&]() {
        #pragma unroll
        for (int i = 0; i < AITER; i++) {
            int slot = tid + i * 256;
            int r = slot / (BK / 4), q = slot % (BK / 4);
            float v[4] = {aR[i].x, aR[i].y, aR[i].z, aR[i].w};
            #pragma unroll
            for (int j = 0; j < 4; j++) {
                unsigned h, l;
                split_tf32(v[j], h, l);
                Ahi[q * 4 + j][r] = h;
                Alo[q * 4 + j][r] = l;
            }
        }
        #pragma unroll
        for (int i = 0; i < BITER; i++) {
            int slot = tid + i * 256;
            int kr = slot / (BN / 4), nc = slot % (BN / 4);
            float v[4] = {bR[i].x, bR[i].y, bR[i].z, bR[i].w};
            #pragma unroll
            for (int j = 0; j < 4; j++) {
                unsigned h, l;
                split_tf32(v[j], h, l);
                Bhi[kr][nc * 4 + j] = h;
                Blo[kr][nc * 4 + j] = l;
            }
        }
    };

    float acc[2][NFRAG][4];
    #pragma unroll
    for (int i = 0; i < 2; i++)
        #pragma unroll
        for (int j = 0; j < NFRAG; j++)
            #pragma unroll
            for (int q = 0; q < 4; q++) acc[i][j][q] = 0.f;

    int tiles = k / BK;
    loadTile(0);
    storeTile();
    __syncthreads();

    for (int t = 0; t < tiles; t++) {
        if (t + 1 < tiles) loadTile((t + 1) * BK);
        #pragma unroll
        for (int ks = 0; ks < BK / 8; ks++) {
            int k0 = ks * 8;
            unsigned ah[2][4], al[2][4];
            #pragma unroll
            for (int mf = 0; mf < 2; mf++) {
                int rb = wm * 32 + mf * 16;
                ah[mf][0] = Ahi[k0 + t4][rb + g];
                ah[mf][1] = Ahi[k0 + t4][rb + g + 8];
                ah[mf][2] = Ahi[k0 + t4 + 4][rb + g];
                ah[mf][3] = Ahi[k0 + t4 + 4][rb + g + 8];
                al[mf][0] = Alo[k0 + t4][rb + g];
                al[mf][1] = Alo[k0 + t4][rb + g + 8];
                al[mf][2] = Alo[k0 + t4 + 4][rb + g];
                al[mf][3] = Alo[k0 + t4 + 4][rb + g + 8];
            }
            unsigned bh[NFRAG][2], bl[NFRAG][2];
            #pragma unroll
            for (int nf = 0; nf < NFRAG; nf++) {
                int cb = wn * WN + nf * 8 + g;
                bh[nf][0] = Bhi[k0 + t4][cb];
                bh[nf][1] = Bhi[k0 + t4 + 4][cb];
                bl[nf][0] = Blo[k0 + t4][cb];
                bl[nf][1] = Blo[k0 + t4 + 4][cb];
            }
            #pragma unroll
            for (int mf = 0; mf < 2; mf++)
                #pragma unroll
                for (int nf = 0; nf < NFRAG; nf++) {
                    float* c = acc[mf][nf];
                    mma_tf32(c[0], c[1], c[2], c[3],
                             ah[mf][0], ah[mf][1], ah[mf][2], ah[mf][3],
                             bh[nf][0], bh[nf][1]);
                    mma_tf32(c[0], c[1], c[2], c[3],
                             ah[mf][0], ah[mf][1], ah[mf][2], ah[mf][3],
                             bl[nf][0], bl[nf][1]);
                    mma_tf32(c[0], c[1], c[2], c[3],
                             al[mf][0], al[mf][1], al[mf][2], al[mf][3],
                             bh[nf][0], bh[nf][1]);
                }
        }
        __syncthreads();
        if (t + 1 < tiles) {
            storeTile();
            __syncthreads();
        }
    }

    // ---- write C tile (fp16) ----
    __half2* C2 = reinterpret_cast<__half2*>(C);
    #pragma unroll
    for (int mf = 0; mf < 2; mf++) {
        int rbase = row0 + wm * 32 + mf * 16;
        #pragma unroll
        for (int nf = 0; nf < NFRAG; nf++) {
            int cb = col0 + wn * WN + nf * 8 + t4 * 2;
            int r0r = rbase + g, r1r = rbase + g + 8;
            if (r0r < n)
                C2[((size_t)r0r * m + cb) >> 1] =
                    __floats2half2_rn(acc[mf][nf][0], acc[mf][nf][1]);
            if (r1r < n)
                C2[((size_t)r1r * m + cb) >> 1] =
                    __floats2half2_rn(acc[mf][nf][2], acc[mf][nf][3]);
        }
    }

    // ---- fused alpha epilogue ----
    {
        float aSv[NFRAG][2], aDv[NFRAG][2];
        int hsel = REDUCE ? 0 : ((col0 + wn * WN) >> 6);
        #pragma unroll
        for (int nf = 0; nf < NFRAG; nf++) {
            int idx = (REDUCE ? wn * WN : 0) + nf * 8 + t4 * 2;
            const float* aS = attS + hsel * 64;
            const float* aD = attD + hsel * 64;
            aSv[nf][0] = aS[idx];     aSv[nf][1] = aS[idx + 1];
            aDv[nf][0] = aD[idx];     aDv[nf][1] = aD[idx + 1];
        }
        if constexpr (REDUCE) {
            __shared__ float sDS[2][BM], sDD[2][BM];
            #pragma unroll
            for (int mf = 0; mf < 2; mf++) {
                float ds0 = 0.f, dd0 = 0.f, ds1 = 0.f, dd1 = 0.f;
                #pragma unroll
                for (int nf = 0; nf < NFRAG; nf++) {
                    ds0 += acc[mf][nf][0] * aSv[nf][0] + acc[mf][nf][1] * aSv[nf][1];
                    dd0 += acc[mf][nf][0] * aDv[nf][0] + acc[mf][nf][1] * aDv[nf][1];
                    ds1 += acc[mf][nf][2] * aSv[nf][0] + acc[mf][nf][3] * aSv[nf][1];
                    dd1 += acc[mf][nf][2] * aDv[nf][0] + acc[mf][nf][3] * aDv[nf][1];
                }
                #pragma unroll
                for (int o = 1; o <= 2; o <<= 1) {
                    ds0 += __shfl_xor_sync(0xffffffffu, ds0, o);
                    dd0 += __shfl_xor_sync(0xffffffffu, dd0, o);
                    ds1 += __shfl_xor_sync(0xffffffffu, ds1, o);
                    dd1 += __shfl_xor_sync(0xffffffffu, dd1, o);
                }
                if (t4 == 0) {
                    int rl = wm * 32 + mf * 16 + g;
                    sDS[wn][rl] = ds0;     sDD[wn][rl] = dd0;
                    sDS[wn][rl + 8] = ds1; sDD[wn][rl + 8] = dd1;
                }
            }
            __syncthreads();
            if (tid < BM) {
                int gr = row0 + tid;
                if (gr < n) {
                    asOut[gr] = sDS[0][tid] + sDS[1][tid];
                    adOut[gr] = sDD[0][tid] + sDD[1][tid];
                }
            }
        } else {
            #pragma unroll
            for (int mf = 0; mf < 2; mf++) {
                float ds0 = 0.f, dd0 = 0.f, ds1 = 0.f, dd1 = 0.f;
                #pragma unroll
                for (int nf = 0; nf < NFRAG; nf++) {
                    ds0 += acc[mf][nf][0] * aSv[nf][0] + acc[mf][nf][1] * aSv[nf][1];
                    dd0 += acc[mf][nf][0] * aDv[nf][0] + acc[mf][nf][1] * aDv[nf][1];
                    ds1 += acc[mf][nf][2] * aSv[nf][0] + acc[mf][nf][3] * aSv[nf][1];
                    dd1 += acc[mf][nf][2] * aDv[nf][0] + acc[mf][nf][3] * aDv[nf][1];
                }
                #pragma unroll
                for (int o = 1; o <= 2; o <<= 1) {
                    ds0 += __shfl_xor_sync(0xffffffffu, ds0, o);
                    dd0 += __shfl_xor_sync(0xffffffffu, dd0, o);
                    ds1 += __shfl_xor_sync(0xffffffffu, ds1, o);
                    dd1 += __shfl_xor_sync(0xffffffffu, dd1, o);
                }
                if (t4 == 0) {
                    int rbase = row0 + wm * 32 + mf * 16;
                    int r0r = rbase + g, r1r = rbase + g + 8;
                    if (r0r < n) { asOut[r0r * 4 + hsel] = ds0; adOut[r0r * 4 + hsel] = dd0; }
                    if (r1r < n) { asOut[r1r * 4 + hsel] = ds1; adOut[r1r * 4 + hsel] = dd1; }
                }
            }
        }
    }
}

// ---------------- fused softmax + aggregation, layer 1 ----------------------
__global__ void agg1_kernel(const float* __restrict__ as1, const float* __restrict__ ad1,
                            const __half* __restrict__ hm, const float* __restrict__ bias,
                            float* __restrict__ out, int n) {
    int tid = threadIdx.x;
    int warp = tid >> 5, lane = tid & 31;
    int node = blockIdx.x * 8 + warp;
    if (node >= n) return;
    int h = lane >> 3;
    int r0 = g_rowptr[node], r1 = g_rowptr[node + 1];
    float adv = ad1[node * 4 + h];
    const uint4* hm4 = reinterpret_cast<const uint4*>(hm);
    float acc[8] = {};
    float dsum = 0.f;
    int j = r0;
    for (; j + 4 <= r1; j += 4) {
        int s0 = __ldg(&g_csrc[j]);
        int s1 = __ldg(&g_csrc[j + 1]);
        int s2 = __ldg(&g_csrc[j + 2]);
        int s3 = __ldg(&g_csrc[j + 3]);
        float e0 = __ldg(&as1[s0 * 4 + h]);
        float e1 = __ldg(&as1[s1 * 4 + h]);
        float e2 = __ldg(&as1[s2 * 4 + h]);
        float e3 = __ldg(&as1[s3 * 4 + h]);
        uint4 v0 = hm4[(size_t)s0 * 32 + lane];
        uint4 v1 = hm4[(size_t)s1 * 32 + lane];
        uint4 v2 = hm4[(size_t)s2 * 32 + lane];
        uint4 v3 = hm4[(size_t)s3 * 32 + lane];
        e0 += adv; e0 = (e0 > 0.f) ? e0 : 0.2f * e0; float w0 = __expf(e0);
        e1 += adv; e1 = (e1 > 0.f) ? e1 : 0.2f * e1; float w1 = __expf(e1);
        e2 += adv; e2 = (e2 > 0.f) ? e2 : 0.2f * e2; float w2 = __expf(e2);
        e3 += adv; e3 = (e3 > 0.f) ? e3 : 0.2f * e3; float w3 = __expf(e3);
        dsum += w0 + w1 + w2 + w3;
        {
            float2 p;
            p = __half22float2(*reinterpret_cast<__half2*>(&v0.x)); acc[0] += p.x * w0; acc[1] += p.y * w0;
            p = __half22float2(*reinterpret_cast<__half2*>(&v0.y)); acc[2] += p.x * w0; acc[3] += p.y * w0;
            p = __half22float2(*reinterpret_cast<__half2*>(&v0.z)); acc[4] += p.x * w0; acc[5] += p.y * w0;
            p = __half22float2(*reinterpret_cast<__half2*>(&v0.w)); acc[6] += p.x * w0; acc[7] += p.y * w0;
            p = __half22float2(*reinterpret_cast<__half2*>(&v1.x)); acc[0] += p.x * w1; acc[1] += p.y * w1;
            p = __half22float2(*reinterpret_cast<__half2*>(&v1.y)); acc[2] += p.x * w1; acc[3] += p.y * w1;
            p = __half22float2(*reinterpret_cast<__half2*>(&v1.z)); acc[4] += p.x * w1; acc[5] += p.y * w1;
            p = __half22float2(*reinterpret_cast<__half2*>(&v1.w)); acc[6] += p.x * w1; acc[7] += p.y * w1;
            p = __half22float2(*reinterpret_cast<__half2*>(&v2.x)); acc[0] += p.x * w2; acc[1] += p.y * w2;
            p = __half22float2(*reinterpret_cast<__half2*>(&v2.y)); acc[2] += p.x * w2; acc[3] += p.y * w2;
            p = __half22float2(*reinterpret_cast<__half2*>(&v2.z)); acc[4] += p.x * w2; acc[5] += p.y * w2;
            p = __half22float2(*reinterpret_cast<__half2*>(&v2.w)); acc[6] += p.x * w2; acc[7] += p.y * w2;
            p = __half22float2(*reinterpret_cast<__half2*>(&v3.x)); acc[0] += p.x * w3; acc[1] += p.y * w3;
            p = __half22float2(*reinterpret_cast<__half2*>(&v3.y)); acc[2] += p.x * w3; acc[3] += p.y * w3;
            p = __half22float2(*reinterpret_cast<__half2*>(&v3.z)); acc[4] += p.x * w3; acc[5] += p.y * w3;
            p = __half22float2(*reinterpret_cast<__half2*>(&v3.w)); acc[6] += p.x * w3; acc[7] += p.y * w3;
        }
    }
    for (; j < r1; j++) {
        int s = __ldg(&g_csrc[j]);
        float e = __ldg(&as1[s * 4 + h]) + adv;
        e = (e > 0.f) ? e : 0.2f * e;
        float w = __expf(e);
        uint4 hv = hm4[(size_t)s * 32 + lane];
        float2 p;
        p = __half22float2(*reinterpret_cast<__half2*>(&hv.x)); acc[0] += p.x * w; acc[1] += p.y * w;
        p = __half22float2(*reinterpret_cast<__half2*>(&hv.y)); acc[2] += p.x * w; acc[3] += p.y * w;
        p = __half22float2(*reinterpret_cast<__half2*>(&hv.z)); acc[4] += p.x * w; acc[5] += p.y * w;
        p = __half22float2(*reinterpret_cast<__half2*>(&hv.w)); acc[6] += p.x * w; acc[7] += p.y * w;
        dsum += w;
    }
    float inv = 1.f / (dsum + 1e-16f);
    size_t ob = (size_t)node * 256 + lane * 8;
    float4 b0 = *reinterpret_cast<const float4*>(&bias[lane * 8]);
    float4 b1 = *reinterpret_cast<const float4*>(&bias[lane * 8 + 4]);
    float o[8];
    o[0] = acc[0] * inv + b0.x; o[1] = acc[1] * inv + b0.y;
    o[2] = acc[2] * inv + b0.z; o[3] = acc[3] * inv + b0.w;
    o[4] = acc[4] * inv + b1.x; o[5] = acc[5] * inv + b1.y;
    o[6] = acc[6] * inv + b1.z; o[7] = acc[7] * inv + b1.w;
    #pragma unroll
    for (int i = 0; i < 8; i++) o[i] = (o[i] > 0.f) ? o[i] : (__expf(o[i]) - 1.f);
    *reinterpret_cast<float4*>(&out[ob])     = make_float4(o[0], o[1], o[2], o[3]);
    *reinterpret_cast<float4*>(&out[ob + 4]) = make_float4(o[4], o[5], o[6], o[7]);
}

// ---------------- fused softmax + aggregation, layer 2 ----------------------
__global__ void agg2_kernel(const float* __restrict__ as2, const float* __restrict__ ad2,
                            const __half* __restrict__ hm, const float* __restrict__ bias,
                            float* __restrict__ out, int n) {
    int tid = threadIdx.x;
    int warp = tid >> 5, lane = tid & 31;
    int node = blockIdx.x * 8 + warp;
    if (node >= n) return;
    int r0 = g_rowptr[node], r1 = g_rowptr[node + 1];
    float adv = ad2[node];
    const __half2* hm2 = reinterpret_cast<const __half2*>(hm);
    float2 acc = make_float2(0.f, 0.f);
    float dsum = 0.f;
    int j = r0;
    for (; j + 4 <= r1; j += 4) {
        int s0 = __ldg(&g_csrc[j]);
        int s1 = __ldg(&g_csrc[j + 1]);
        int s2 = __ldg(&g_csrc[j + 2]);
        int s3 = __ldg(&g_csrc[j + 3]);
        float e0 = __ldg(&as2[s0]);
        float e1 = __ldg(&as2[s1]);
        float e2 = __ldg(&as2[s2]);
        float e3 = __ldg(&as2[s3]);
        float2 v0 = __half22float2(hm2[(size_t)s0 * 32 + lane]);
        float2 v1 = __half22float2(hm2[(size_t)s1 * 32 + lane]);
        float2 v2 = __half22float2(hm2[(size_t)s2 * 32 + lane]);
        float2 v3 = __half22float2(hm2[(size_t)s3 * 32 + lane]);
        e0 += adv; e0 = (e0 > 0.f) ? e0 : 0.2f * e0; float w0 = __expf(e0);
        e1 += adv; e1 = (e1 > 0.f) ? e1 : 0.2f * e1; float w1 = __expf(e1);
        e2 += adv; e2 = (e2 > 0.f) ? e2 : 0.2f * e2; float w2 = __expf(e2);
        e3 += adv; e3 = (e3 > 0.f) ? e3 : 0.2f * e3; float w3 = __expf(e3);
        acc.x += v0.x * w0 + v1.x * w1 + v2.x * w2 + v3.x * w3;
        acc.y += v0.y * w0 + v1.y * w1 + v2.y * w2 + v3.y * w3;
        dsum += w0 + w1 + w2 + w3;
    }
    for (; j < r1; j++) {
        int s = __ldg(&g_csrc[j]);
        float e = __ldg(&as2[s]) + adv;
        e = (e > 0.f) ? e : 0.2f * e;
        float w = __expf(e);
        float2 hv = __half22float2(hm2[(size_t)s * 32 + lane]);
        acc.x += hv.x * w; acc.y += hv.y * w;
        dsum += w;
    }
    float inv = 1.f / (dsum + 1e-16f);
    float2 bv = *reinterpret_cast<const float2*>(&bias[lane * 2]);
    *reinterpret_cast<float2*>(&out[(size_t)node * 64 + lane * 2]) =
        make_float2(acc.x * inv + bv.x, acc.y * inv + bv.y);
}

// ---------------- launch ----------------------------------------------------
extern "C" void kernel_launch(void* const* d_in, const int* in_sizes, int n_in,
                              void* d_out, int out_size) {
    const float* x   = (const float*)d_in[0];
    const int*   ei  = (const int*)d_in[1];
    const float* W1  = (const float*)d_in[2];
    const float* a1s = (const float*)d_in[3];
    const float* a1d = (const float*)d_in[4];
    const float* b1  = (const float*)d_in[5];
    const float* W2  = (const float*)d_in[6];
    const float* a2s = (const float*)d_in[7];
    const float* a2d = (const float*)d_in[8];
    const float* b2  = (const float*)d_in[9];
    float* out = (float*)d_out;

    int N = in_sizes[0] / 128;
    int E = in_sizes[1] / 2;
    int EPN = E + N;
    int NB = (N + 1023) / 1024;
    int EQN = (E >> 2) + N;   // batched edge items + self-loops

    float *out1, *as1, *ad1, *as2, *ad2;
    __half *h1, *h2;
    cudaGetSymbolAddress((void**)&h1,   g_h1);
    cudaGetSymbolAddress((void**)&out1, g_out1);
    cudaGetSymbolAddress((void**)&h2,   g_h2);
    cudaGetSymbolAddress((void**)&as1,  g_as1);
    cudaGetSymbolAddress((void**)&ad1,  g_ad1);
    cudaGetSymbolAddress((void**)&as2,  g_as2);
    cudaGetSymbolAddress((void**)&ad2,  g_ad2);

    cudaStream_t s2 = g_res.s2;

    // fork: CSR build on s2, GEMM1 on the main (capture) stream
    cudaEventRecord(g_res.evFork, 0);
    cudaStreamWaitEvent(s2, g_res.evFork, 0);

    hist_kernel<<<(EQN + 255) / 256, 256, 0, s2>>>(ei, E, N);
    scan_local_kernel<<<NB, 1024, 0, s2>>>(N);
    scan_add_kernel<<<(N + 255) / 256, 256, 0, s2>>>(N, EPN, NB);
    scatter_kernel<<<(EQN + 255) / 256, 256, 0, s2>>>(ei, E, N);
    cudaEventRecord(g_res.evJoin, s2);

    gemm_tc_kernel<128, false><<<dim3(2, (N + 127) / 128), 256>>>(
        x, W1, h1, N, 128, 256, a1s, a1d, as1, ad1);

    // join: agg1 needs both the CSR and GEMM1 outputs
    cudaStreamWaitEvent(0, g_res.evJoin, 0);

    agg1_kernel<<<(N + 7) / 8, 256>>>(as1, ad1, h1, b1, out1, N);

    gemm_tc_kernel<64, true><<<dim3(1, (N + 127) / 128), 256>>>(
        out1, W2, h2, N, 256, 64, a2s, a2d, as2, ad2);
    agg2_kernel<<<(N + 7) / 8, 256>>>(as2, ad2, h2, b2, out, N);
}